// round 1
// baseline (speedup 1.0000x reference)
#include <cuda_runtime.h>
#include <math.h>

#define LDIM 384
#define NSEQ 512
#define DIN 128
#define DOUT 64
#define HEADS 4
#define DFF 256
#define TOK (NSEQ*LDIM)      // 196608
#define CHUNK 49152          // TOK/4

// ---------------- scratch (device globals; reused across phases) ------------
__device__ float g_attn[HEADS*LDIM*LDIM];   // logits -> softmax (2.36 MB)
__device__ float g_lnT[TOK*DOUT];           // LN(tgt), later LN(mid)   (50 MB)
__device__ float g_v[TOK*DOUT];             // v transposed [h][n][c][k]; later mid (50 MB)
__device__ float g_o[TOK*DOUT];             // attention out [n][l][64]; later FFN hidden chunk (50 MB)

__device__ __forceinline__ float warpSum(float v) {
#pragma unroll
    for (int o = 16; o > 0; o >>= 1) v += __shfl_xor_sync(0xffffffffu, v, o);
    return v;
}

// ---------------- kernel 1: symmetrize + LN(128) + @Wp + bp -> logits -------
// one warp per (k,l) pair
__global__ __launch_bounds__(256) void k_logits(
    const float* __restrict__ src, const float* __restrict__ Wp,
    const float* __restrict__ bp, const float* __restrict__ gn,
    const float* __restrict__ btn)
{
    int warp = (blockIdx.x * blockDim.x + threadIdx.x) >> 5;
    int lane = threadIdx.x & 31;
    if (warp >= LDIM * LDIM) return;
    int k = warp / LDIM, l = warp % LDIM;

    float4 a = *(const float4*)(src + ((size_t)k * LDIM + l) * DIN + lane * 4);
    float4 b = *(const float4*)(src + ((size_t)l * LDIM + k) * DIN + lane * 4);
    float x0 = 0.5f * (a.x + b.x), x1 = 0.5f * (a.y + b.y);
    float x2 = 0.5f * (a.z + b.z), x3 = 0.5f * (a.w + b.w);

    float m = warpSum(x0 + x1 + x2 + x3) * (1.0f / 128.0f);
    float d0 = x0 - m, d1 = x1 - m, d2 = x2 - m, d3 = x3 - m;
    float var = warpSum(d0*d0 + d1*d1 + d2*d2 + d3*d3) * (1.0f / 128.0f);
    float rinv = rsqrtf(var + 1e-5f);

    int i0 = lane * 4;
    float4 g  = *(const float4*)(gn  + i0);
    float4 bt = *(const float4*)(btn + i0);
    float y0 = g.x * d0 * rinv + bt.x;
    float y1 = g.y * d1 * rinv + bt.y;
    float y2 = g.z * d2 * rinv + bt.z;
    float y3 = g.w * d3 * rinv + bt.w;

    const float4* Wp4 = (const float4*)Wp;      // row d -> 4 head weights
    float4 w0 = Wp4[i0 + 0], w1 = Wp4[i0 + 1], w2 = Wp4[i0 + 2], w3 = Wp4[i0 + 3];

    float h0 = y0*w0.x + y1*w1.x + y2*w2.x + y3*w3.x;
    float h1 = y0*w0.y + y1*w1.y + y2*w2.y + y3*w3.y;
    float h2 = y0*w0.z + y1*w1.z + y2*w2.z + y3*w3.z;
    float h3 = y0*w0.w + y1*w1.w + y2*w2.w + y3*w3.w;
    h0 = warpSum(h0); h1 = warpSum(h1); h2 = warpSum(h2); h3 = warpSum(h3);

    if (lane == 0) {
        size_t p = (size_t)k * LDIM + l;
        g_attn[0 * LDIM * LDIM + p] = h0 + bp[0];
        g_attn[1 * LDIM * LDIM + p] = h1 + bp[1];
        g_attn[2 * LDIM * LDIM + p] = h2 + bp[2];
        g_attn[3 * LDIM * LDIM + p] = h3 + bp[3];
    }
}

// ---------------- kernel 2: softmax over k (in place, column (h,l)) ---------
__global__ __launch_bounds__(128) void k_softmax()
{
    int h = blockIdx.x / LDIM;
    int l = blockIdx.x % LDIM;
    float* base = g_attn + (size_t)h * LDIM * LDIM + l;
    int t = threadIdx.x;   // 128 threads, 3 elems each

    float v0 = base[(size_t)(t      ) * LDIM];
    float v1 = base[(size_t)(t + 128) * LDIM];
    float v2 = base[(size_t)(t + 256) * LDIM];

    __shared__ float red[128];
    red[t] = fmaxf(v0, fmaxf(v1, v2));
    __syncthreads();
#pragma unroll
    for (int s = 64; s > 0; s >>= 1) {
        if (t < s) red[t] = fmaxf(red[t], red[t + s]);
        __syncthreads();
    }
    float mx = red[0];
    __syncthreads();

    float e0 = __expf(v0 - mx), e1 = __expf(v1 - mx), e2 = __expf(v2 - mx);
    red[t] = e0 + e1 + e2;
    __syncthreads();
#pragma unroll
    for (int s = 64; s > 0; s >>= 1) {
        if (t < s) red[t] += red[t + s];
        __syncthreads();
    }
    float rs = 1.0f / red[0];

    base[(size_t)(t      ) * LDIM] = e0 * rs;
    base[(size_t)(t + 128) * LDIM] = e1 * rs;
    base[(size_t)(t + 256) * LDIM] = e2 * rs;
}

// ---------------- LN over 64 (warp per token) -> g_lnT ----------------------
__global__ __launch_bounds__(256) void k_ln64(
    const float* __restrict__ Xin, const float* __restrict__ g,
    const float* __restrict__ b, int sel)
{
    const float* X = sel ? (const float*)g_v : Xin;
    int warp = (blockIdx.x * blockDim.x + threadIdx.x) >> 5;
    int lane = threadIdx.x & 31;
    if (warp >= TOK) return;
    const float* x = X + (size_t)warp * 64 + lane * 2;
    float2 v = *(const float2*)x;
    float m = warpSum(v.x + v.y) * (1.0f / 64.0f);
    float d0 = v.x - m, d1 = v.y - m;
    float var = warpSum(d0*d0 + d1*d1) * (1.0f / 64.0f);
    float rinv = rsqrtf(var + 1e-5f);
    float2 gg = *(const float2*)(g + lane * 2);
    float2 bb = *(const float2*)(b + lane * 2);
    float2 o;
    o.x = gg.x * d0 * rinv + bb.x;
    o.y = gg.y * d1 * rinv + bb.y;
    *(float2*)(g_lnT + (size_t)warp * 64 + lane * 2) = o;
}

// ---------------- generic 64x64x16 fp32 GEMM with epilogue ------------------
// A [M,K] row-major, B [K,N] row-major. M%64==0, N%64==0, K%16==0. 256 thr.
template <class Epi>
__global__ __launch_bounds__(256) void k_gemm(
    const float* __restrict__ A, const float* __restrict__ B,
    int M, int N, int K, long sA, long sB, Epi epi)
{
    __shared__ float As[16][64];
    __shared__ float Bs[16][64];
    const float* Ab = A + (size_t)blockIdx.z * sA;
    const float* Bb = B + (size_t)blockIdx.z * sB;
    int bm = blockIdx.y * 64, bn = blockIdx.x * 64;
    int tid = threadIdx.x;
    int tx = tid & 15, ty = tid >> 4;
    int arow = tid >> 2, acol = (tid & 3) * 4;
    int brow = tid >> 4, bcol = (tid & 15) * 4;

    float acc[4][4] = {{0.f}};

    for (int k0 = 0; k0 < K; k0 += 16) {
        float4 av = *(const float4*)(Ab + (size_t)(bm + arow) * K + k0 + acol);
        As[acol + 0][arow] = av.x;
        As[acol + 1][arow] = av.y;
        As[acol + 2][arow] = av.z;
        As[acol + 3][arow] = av.w;
        *(float4*)(&Bs[brow][bcol]) =
            *(const float4*)(Bb + (size_t)(k0 + brow) * N + bn + bcol);
        __syncthreads();
#pragma unroll
        for (int kk = 0; kk < 16; kk++) {
            float4 a = *(const float4*)(&As[kk][ty * 4]);
            float4 b = *(const float4*)(&Bs[kk][tx * 4]);
            acc[0][0] += a.x*b.x; acc[0][1] += a.x*b.y; acc[0][2] += a.x*b.z; acc[0][3] += a.x*b.w;
            acc[1][0] += a.y*b.x; acc[1][1] += a.y*b.y; acc[1][2] += a.y*b.z; acc[1][3] += a.y*b.w;
            acc[2][0] += a.z*b.x; acc[2][1] += a.z*b.y; acc[2][2] += a.z*b.z; acc[2][3] += a.z*b.w;
            acc[3][0] += a.w*b.x; acc[3][1] += a.w*b.y; acc[3][2] += a.w*b.z; acc[3][3] += a.w*b.w;
        }
        __syncthreads();
    }
#pragma unroll
    for (int i = 0; i < 4; i++)
#pragma unroll
        for (int j = 0; j < 4; j++)
            epi(blockIdx.z, bm + ty * 4 + i, bn + tx * 4 + j, acc[i][j]);
}

// ---------------- epilogues -------------------------------------------------
struct EpiV {                    // v = LN(tgt)@Wm + bm, scatter to [h][n][c][k]
    const float* bias;
    __device__ void operator()(int, int row, int col, float val) const {
        val += bias[col];
        int n = row / LDIM, k = row % LDIM;
        int c = col >> 2, h = col & 3;
        g_v[(((size_t)h * NSEQ + n) * 16 + c) * LDIM + k] = val;
    }
};
struct EpiAttn {                 // o[n][l][c*4+h] = v_h @ attn_h
    __device__ void operator()(int h, int row, int col, float val) const {
        int n = row >> 4, c = row & 15;
        g_o[((size_t)n * LDIM + col) * 64 + c * 4 + h] = val;
    }
};
struct EpiWo {                   // mid = o@Wo + bo + tgt   (mid lives in g_v)
    const float* bo; const float* tgt;
    __device__ void operator()(int, int row, int col, float val) const {
        size_t i = (size_t)row * 64 + col;
        g_v[i] = val + bo[col] + tgt[i];
    }
};
struct EpiW1 {                   // h1 = relu(LN(mid)@W1 + b1)   (h1 in g_o)
    const float* b1;
    __device__ void operator()(int, int row, int col, float val) const {
        g_o[(size_t)row * DFF + col] = fmaxf(val + b1[col], 0.0f);
    }
};
struct EpiW2 {                   // out = mid + h1@W2 + b2
    const float* b2; float* out; int off;
    __device__ void operator()(int, int row, int col, float val) const {
        size_t i = (size_t)(row + off) * 64 + col;
        out[i] = val + b2[col] + g_v[i];
    }
};

// ---------------- launch ----------------------------------------------------
extern "C" void kernel_launch(void* const* d_in, const int* in_sizes, int n_in,
                              void* d_out, int out_size)
{
    const float* src = (const float*)d_in[0];
    const float* tgt = (const float*)d_in[1];
    const float* Wp  = (const float*)d_in[2];
    const float* bp  = (const float*)d_in[3];
    const float* Wm  = (const float*)d_in[4];
    const float* bm  = (const float*)d_in[5];
    const float* Wo  = (const float*)d_in[6];
    const float* bo  = (const float*)d_in[7];
    const float* W1  = (const float*)d_in[8];
    const float* b1  = (const float*)d_in[9];
    const float* W2  = (const float*)d_in[10];
    const float* b2  = (const float*)d_in[11];
    const float* gn  = (const float*)d_in[12];
    const float* btn = (const float*)d_in[13];
    const float* g1  = (const float*)d_in[14];
    const float* bt1 = (const float*)d_in[15];
    const float* g2  = (const float*)d_in[16];
    const float* bt2 = (const float*)d_in[17];
    float* out = (float*)d_out;

    float *p_attn = nullptr, *p_lnT = nullptr, *p_v = nullptr, *p_o = nullptr;
    cudaGetSymbolAddress((void**)&p_attn, g_attn);
    cudaGetSymbolAddress((void**)&p_lnT,  g_lnT);
    cudaGetSymbolAddress((void**)&p_v,    g_v);
    cudaGetSymbolAddress((void**)&p_o,    g_o);

    // 1) pair logits (symmetrize + LN128 + @Wp)
    k_logits<<<(LDIM * LDIM) / 8, 256>>>(src, Wp, bp, gn, btn);
    // 2) softmax over k
    k_softmax<<<HEADS * LDIM, 128>>>();
    // 3) LN(tgt) -> g_lnT
    k_ln64<<<TOK / 8, 256>>>(tgt, g1, bt1, 0);
    // 4) v = LN(tgt)@Wm + bm, transposed-scatter into g_v [h][n][c][k]
    k_gemm<<<dim3(1, TOK / 64, 1), 256>>>(p_lnT, Wm, TOK, 64, 64, 0, 0, EpiV{bm});
    // 5) per-head GEMM: o = v_h @ attn_h
    k_gemm<<<dim3(LDIM / 64, (NSEQ * 16) / 64, HEADS), 256>>>(
        p_v, p_attn, NSEQ * 16, LDIM, LDIM,
        (long)NSEQ * 16 * LDIM, (long)LDIM * LDIM, EpiAttn{});
    // 6) mid = o@Wo + bo + tgt   (into g_v)
    k_gemm<<<dim3(1, TOK / 64, 1), 256>>>(p_o, Wo, TOK, 64, 64, 0, 0, EpiWo{bo, tgt});
    // 7) LN(mid) -> g_lnT
    k_ln64<<<TOK / 8, 256>>>(nullptr, g2, bt2, 1);
    // 8) FFN in 4 chunks (hidden buffer reuses g_o)
    for (int c = 0; c < 4; c++) {
        int off = c * CHUNK;
        k_gemm<<<dim3(DFF / 64, CHUNK / 64, 1), 256>>>(
            p_lnT + (size_t)off * 64, W1, CHUNK, DFF, 64, 0, 0, EpiW1{b1});
        k_gemm<<<dim3(1, CHUNK / 64, 1), 256>>>(
            p_o, W2, CHUNK, 64, DFF, 0, 0, EpiW2{b2, out, off});
    }
}

// round 2
// speedup vs baseline: 1.8262x; 1.8262x over previous
#include <cuda_runtime.h>
#include <math.h>
#include <stdint.h>

#define LDIM 384
#define NSEQ 512
#define DIN 128
#define DOUT 64
#define HEADS 4
#define DFF 256
#define TOK (NSEQ*LDIM)      // 196608
#define CHUNK 49152          // TOK/4

// ---------------- scratch (device globals; reused across phases) ------------
__device__ float g_attn[HEADS*LDIM*LDIM];   // logits -> softmax (2.36 MB)
__device__ float g_lnT[TOK*DOUT];           // LN(tgt), later LN(mid)   (50 MB)
__device__ float g_v[TOK*DOUT];             // v transposed [h][n][c][k]; later mid (50 MB)
__device__ float g_o[TOK*DFF/4];            // attention out; later FFN hidden chunk (50 MB)

__device__ __forceinline__ float warpSum(float v) {
#pragma unroll
    for (int o = 16; o > 0; o >>= 1) v += __shfl_xor_sync(0xffffffffu, v, o);
    return v;
}

__device__ __forceinline__ uint32_t f2tf(float f) {
    uint32_t u;
    asm("cvt.rna.tf32.f32 %0, %1;" : "=r"(u) : "f"(f));
    return u;
}

// ---------------- kernel 1: symmetrize + LN(128) + @Wp + bp -> logits -------
__global__ __launch_bounds__(256) void k_logits(
    const float* __restrict__ src, const float* __restrict__ Wp,
    const float* __restrict__ bp, const float* __restrict__ gn,
    const float* __restrict__ btn)
{
    int warp = (blockIdx.x * blockDim.x + threadIdx.x) >> 5;
    int lane = threadIdx.x & 31;
    if (warp >= LDIM * LDIM) return;
    int k = warp / LDIM, l = warp % LDIM;

    float4 a = *(const float4*)(src + ((size_t)k * LDIM + l) * DIN + lane * 4);
    float4 b = *(const float4*)(src + ((size_t)l * LDIM + k) * DIN + lane * 4);
    float x0 = 0.5f * (a.x + b.x), x1 = 0.5f * (a.y + b.y);
    float x2 = 0.5f * (a.z + b.z), x3 = 0.5f * (a.w + b.w);

    float m = warpSum(x0 + x1 + x2 + x3) * (1.0f / 128.0f);
    float d0 = x0 - m, d1 = x1 - m, d2 = x2 - m, d3 = x3 - m;
    float var = warpSum(d0*d0 + d1*d1 + d2*d2 + d3*d3) * (1.0f / 128.0f);
    float rinv = rsqrtf(var + 1e-5f);

    int i0 = lane * 4;
    float4 g  = *(const float4*)(gn  + i0);
    float4 bt = *(const float4*)(btn + i0);
    float y0 = g.x * d0 * rinv + bt.x;
    float y1 = g.y * d1 * rinv + bt.y;
    float y2 = g.z * d2 * rinv + bt.z;
    float y3 = g.w * d3 * rinv + bt.w;

    const float4* Wp4 = (const float4*)Wp;
    float4 w0 = Wp4[i0 + 0], w1 = Wp4[i0 + 1], w2 = Wp4[i0 + 2], w3 = Wp4[i0 + 3];

    float h0 = y0*w0.x + y1*w1.x + y2*w2.x + y3*w3.x;
    float h1 = y0*w0.y + y1*w1.y + y2*w2.y + y3*w3.y;
    float h2 = y0*w0.z + y1*w1.z + y2*w2.z + y3*w3.z;
    float h3 = y0*w0.w + y1*w1.w + y2*w2.w + y3*w3.w;
    h0 = warpSum(h0); h1 = warpSum(h1); h2 = warpSum(h2); h3 = warpSum(h3);

    if (lane == 0) {
        size_t p = (size_t)k * LDIM + l;
        g_attn[0 * LDIM * LDIM + p] = h0 + bp[0];
        g_attn[1 * LDIM * LDIM + p] = h1 + bp[1];
        g_attn[2 * LDIM * LDIM + p] = h2 + bp[2];
        g_attn[3 * LDIM * LDIM + p] = h3 + bp[3];
    }
}

// ---------------- kernel 2: softmax over k (in place, column (h,l)) ---------
__global__ __launch_bounds__(128) void k_softmax()
{
    int h = blockIdx.x / LDIM;
    int l = blockIdx.x % LDIM;
    float* base = g_attn + (size_t)h * LDIM * LDIM + l;
    int t = threadIdx.x;

    float v0 = base[(size_t)(t      ) * LDIM];
    float v1 = base[(size_t)(t + 128) * LDIM];
    float v2 = base[(size_t)(t + 256) * LDIM];

    __shared__ float red[128];
    red[t] = fmaxf(v0, fmaxf(v1, v2));
    __syncthreads();
#pragma unroll
    for (int s = 64; s > 0; s >>= 1) {
        if (t < s) red[t] = fmaxf(red[t], red[t + s]);
        __syncthreads();
    }
    float mx = red[0];
    __syncthreads();

    float e0 = __expf(v0 - mx), e1 = __expf(v1 - mx), e2 = __expf(v2 - mx);
    red[t] = e0 + e1 + e2;
    __syncthreads();
#pragma unroll
    for (int s = 64; s > 0; s >>= 1) {
        if (t < s) red[t] += red[t + s];
        __syncthreads();
    }
    float rs = 1.0f / red[0];

    base[(size_t)(t      ) * LDIM] = e0 * rs;
    base[(size_t)(t + 128) * LDIM] = e1 * rs;
    base[(size_t)(t + 256) * LDIM] = e2 * rs;
}

// ---------------- LN over 64 (warp per token) -> g_lnT ----------------------
__global__ __launch_bounds__(256) void k_ln64(
    const float* __restrict__ Xin, const float* __restrict__ g,
    const float* __restrict__ b, int sel)
{
    const float* X = sel ? (const float*)g_v : Xin;
    int warp = (blockIdx.x * blockDim.x + threadIdx.x) >> 5;
    int lane = threadIdx.x & 31;
    if (warp >= TOK) return;
    const float* x = X + (size_t)warp * 64 + lane * 2;
    float2 v = *(const float2*)x;
    float m = warpSum(v.x + v.y) * (1.0f / 64.0f);
    float d0 = v.x - m, d1 = v.y - m;
    float var = warpSum(d0*d0 + d1*d1) * (1.0f / 64.0f);
    float rinv = rsqrtf(var + 1e-5f);
    float2 gg = *(const float2*)(g + lane * 2);
    float2 bb = *(const float2*)(b + lane * 2);
    float2 o;
    o.x = gg.x * d0 * rinv + bb.x;
    o.y = gg.y * d1 * rinv + bb.y;
    *(float2*)(g_lnT + (size_t)warp * 64 + lane * 2) = o;
}

// =================== tf32 tensor-core GEMM ===================================
// A [M,K] row-major, B [K,N] row-major, fp32 in, tf32 mma, fp32 accum.
// Block tile 128(M) x 64(N), K-step 16, 8 warps (4m x 2n), warp tile 32x32.
// Requirements: M%128==0, N%64==0, K%16==0.
#define AS_STRIDE 20
#define BS_STRIDE 72

__device__ __forceinline__ void mma_tf32(
    float& c0, float& c1, float& c2, float& c3,
    uint32_t a0, uint32_t a1, uint32_t a2, uint32_t a3,
    uint32_t b0, uint32_t b1)
{
    asm volatile(
        "mma.sync.aligned.m16n8k8.row.col.f32.tf32.tf32.f32 "
        "{%0,%1,%2,%3},{%4,%5,%6,%7},{%8,%9},{%0,%1,%2,%3};"
        : "+f"(c0), "+f"(c1), "+f"(c2), "+f"(c3)
        : "r"(a0), "r"(a1), "r"(a2), "r"(a3), "r"(b0), "r"(b1));
}

template <class Epi>
__global__ __launch_bounds__(256) void k_mma(
    const float* __restrict__ A, const float* __restrict__ B,
    int M, int N, int K, long sA, long sB, Epi epi)
{
    __shared__ uint32_t As[2][128 * AS_STRIDE];
    __shared__ uint32_t Bs[2][16 * BS_STRIDE];

    const float* Ab = A + (size_t)blockIdx.z * sA;
    const float* Bb = B + (size_t)blockIdx.z * sB;
    int bm = blockIdx.y * 128, bn = blockIdx.x * 64;

    int tid  = threadIdx.x;
    int lane = tid & 31, wid = tid >> 5;
    int wm = wid >> 1, wn = wid & 1;
    int grp = lane >> 2, tig = lane & 3;

    // staging thread mapping
    int ar  = tid >> 2;            // A rows ar and ar+64
    int ac4 = (tid & 3) * 4;       // A k-offset
    int bk  = tid >> 4;            // B k row
    int bn4 = (tid & 15) * 4;      // B n-offset

    float c[2][4][4];
#pragma unroll
    for (int i = 0; i < 2; i++)
#pragma unroll
        for (int j = 0; j < 4; j++)
#pragma unroll
            for (int q = 0; q < 4; q++) c[i][j][q] = 0.f;

    float4 ra0, ra1, rb;
    // prologue: load stage 0
    ra0 = *(const float4*)(Ab + (size_t)(bm + ar) * K + ac4);
    ra1 = *(const float4*)(Ab + (size_t)(bm + ar + 64) * K + ac4);
    rb  = *(const float4*)(Bb + (size_t)bk * N + bn + bn4);
    {
        uint32_t* dA = &As[0][ar * AS_STRIDE + ac4];
        dA[0] = f2tf(ra0.x); dA[1] = f2tf(ra0.y); dA[2] = f2tf(ra0.z); dA[3] = f2tf(ra0.w);
        uint32_t* dA1 = &As[0][(ar + 64) * AS_STRIDE + ac4];
        dA1[0] = f2tf(ra1.x); dA1[1] = f2tf(ra1.y); dA1[2] = f2tf(ra1.z); dA1[3] = f2tf(ra1.w);
        uint32_t* dB = &Bs[0][bk * BS_STRIDE + bn4];
        dB[0] = f2tf(rb.x); dB[1] = f2tf(rb.y); dB[2] = f2tf(rb.z); dB[3] = f2tf(rb.w);
    }
    __syncthreads();

    int nstage = K >> 4;
    for (int s = 0; s < nstage; s++) {
        int buf = s & 1;
        bool more = (s + 1) < nstage;
        if (more) {
            int k0 = (s + 1) << 4;
            ra0 = *(const float4*)(Ab + (size_t)(bm + ar) * K + k0 + ac4);
            ra1 = *(const float4*)(Ab + (size_t)(bm + ar + 64) * K + k0 + ac4);
            rb  = *(const float4*)(Bb + (size_t)(k0 + bk) * N + bn + bn4);
        }
        const uint32_t* As_ = &As[buf][0];
        const uint32_t* Bs_ = &Bs[buf][0];
#pragma unroll
        for (int ks = 0; ks < 2; ks++) {
            uint32_t a[2][4], b[4][2];
            int arow = wm * 32 + grp;
            int acol = ks * 8 + tig;
#pragma unroll
            for (int mt = 0; mt < 2; mt++) {
                a[mt][0] = As_[(arow + mt * 16    ) * AS_STRIDE + acol];
                a[mt][1] = As_[(arow + mt * 16 + 8) * AS_STRIDE + acol];
                a[mt][2] = As_[(arow + mt * 16    ) * AS_STRIDE + acol + 4];
                a[mt][3] = As_[(arow + mt * 16 + 8) * AS_STRIDE + acol + 4];
            }
#pragma unroll
            for (int nt = 0; nt < 4; nt++) {
                int bcol = wn * 32 + nt * 8 + grp;
                b[nt][0] = Bs_[(ks * 8 + tig    ) * BS_STRIDE + bcol];
                b[nt][1] = Bs_[(ks * 8 + tig + 4) * BS_STRIDE + bcol];
            }
#pragma unroll
            for (int mt = 0; mt < 2; mt++)
#pragma unroll
                for (int nt = 0; nt < 4; nt++)
                    mma_tf32(c[mt][nt][0], c[mt][nt][1], c[mt][nt][2], c[mt][nt][3],
                             a[mt][0], a[mt][1], a[mt][2], a[mt][3],
                             b[nt][0], b[nt][1]);
        }
        if (more) {
            int nbuf = buf ^ 1;
            uint32_t* dA = &As[nbuf][ar * AS_STRIDE + ac4];
            dA[0] = f2tf(ra0.x); dA[1] = f2tf(ra0.y); dA[2] = f2tf(ra0.z); dA[3] = f2tf(ra0.w);
            uint32_t* dA1 = &As[nbuf][(ar + 64) * AS_STRIDE + ac4];
            dA1[0] = f2tf(ra1.x); dA1[1] = f2tf(ra1.y); dA1[2] = f2tf(ra1.z); dA1[3] = f2tf(ra1.w);
            uint32_t* dB = &Bs[nbuf][bk * BS_STRIDE + bn4];
            dB[0] = f2tf(rb.x); dB[1] = f2tf(rb.y); dB[2] = f2tf(rb.z); dB[3] = f2tf(rb.w);
        }
        __syncthreads();
    }

    // epilogue
#pragma unroll
    for (int mt = 0; mt < 2; mt++)
#pragma unroll
        for (int nt = 0; nt < 4; nt++) {
            int row = bm + wm * 32 + mt * 16 + grp;
            int col = bn + wn * 32 + nt * 8 + 2 * tig;
            epi(blockIdx.z, row,     col,     c[mt][nt][0]);
            epi(blockIdx.z, row,     col + 1, c[mt][nt][1]);
            epi(blockIdx.z, row + 8, col,     c[mt][nt][2]);
            epi(blockIdx.z, row + 8, col + 1, c[mt][nt][3]);
        }
}

// ---------------- epilogues -------------------------------------------------
struct EpiV {                    // v = LN(tgt)@Wm + bm, scatter to [h][n][c][k]
    const float* bias;
    __device__ void operator()(int, int row, int col, float val) const {
        val += bias[col];
        int n = row / LDIM, k = row % LDIM;
        int c = col >> 2, h = col & 3;
        g_v[(((size_t)h * NSEQ + n) * 16 + c) * LDIM + k] = val;
    }
};
struct EpiAttn {                 // o[n][l][c*4+h] = v_h @ attn_h
    __device__ void operator()(int h, int row, int col, float val) const {
        int n = row >> 4, c = row & 15;
        g_o[((size_t)n * LDIM + col) * 64 + c * 4 + h] = val;
    }
};
struct EpiWo {                   // mid = o@Wo + bo + tgt   (mid lives in g_v)
    const float* bo; const float* tgt;
    __device__ void operator()(int, int row, int col, float val) const {
        size_t i = (size_t)row * 64 + col;
        g_v[i] = val + bo[col] + tgt[i];
    }
};
struct EpiW1 {                   // h1 = relu(LN(mid)@W1 + b1)   (h1 in g_o)
    const float* b1;
    __device__ void operator()(int, int row, int col, float val) const {
        g_o[(size_t)row * DFF + col] = fmaxf(val + b1[col], 0.0f);
    }
};
struct EpiW2 {                   // out = mid + h1@W2 + b2
    const float* b2; float* out; int off;
    __device__ void operator()(int, int row, int col, float val) const {
        size_t i = (size_t)(row + off) * 64 + col;
        out[i] = val + b2[col] + g_v[i];
    }
};

// ---------------- launch ----------------------------------------------------
extern "C" void kernel_launch(void* const* d_in, const int* in_sizes, int n_in,
                              void* d_out, int out_size)
{
    const float* src = (const float*)d_in[0];
    const float* tgt = (const float*)d_in[1];
    const float* Wp  = (const float*)d_in[2];
    const float* bp  = (const float*)d_in[3];
    const float* Wm  = (const float*)d_in[4];
    const float* bm  = (const float*)d_in[5];
    const float* Wo  = (const float*)d_in[6];
    const float* bo  = (const float*)d_in[7];
    const float* W1  = (const float*)d_in[8];
    const float* b1  = (const float*)d_in[9];
    const float* W2  = (const float*)d_in[10];
    const float* b2  = (const float*)d_in[11];
    const float* gn  = (const float*)d_in[12];
    const float* btn = (const float*)d_in[13];
    const float* g1  = (const float*)d_in[14];
    const float* bt1 = (const float*)d_in[15];
    const float* g2  = (const float*)d_in[16];
    const float* bt2 = (const float*)d_in[17];
    float* out = (float*)d_out;

    float *p_attn = nullptr, *p_lnT = nullptr, *p_v = nullptr, *p_o = nullptr;
    cudaGetSymbolAddress((void**)&p_attn, g_attn);
    cudaGetSymbolAddress((void**)&p_lnT,  g_lnT);
    cudaGetSymbolAddress((void**)&p_v,    g_v);
    cudaGetSymbolAddress((void**)&p_o,    g_o);

    // 1) pair logits (symmetrize + LN128 + @Wp)
    k_logits<<<(LDIM * LDIM) / 8, 256>>>(src, Wp, bp, gn, btn);
    // 2) softmax over k
    k_softmax<<<HEADS * LDIM, 128>>>();
    // 3) LN(tgt) -> g_lnT
    k_ln64<<<TOK / 8, 256>>>(tgt, g1, bt1, 0);
    // 4) v = LN(tgt)@Wm + bm, transposed-scatter into g_v [h][n][c][k]
    k_mma<<<dim3(1, TOK / 128, 1), 256>>>(p_lnT, Wm, TOK, 64, 64, 0, 0, EpiV{bm});
    // 5) per-head GEMM: o = v_h @ attn_h
    k_mma<<<dim3(LDIM / 64, (NSEQ * 16) / 128, HEADS), 256>>>(
        p_v, p_attn, NSEQ * 16, LDIM, LDIM,
        (long)NSEQ * 16 * LDIM, (long)LDIM * LDIM, EpiAttn{});
    // 6) mid = o@Wo + bo + tgt   (into g_v)
    k_mma<<<dim3(1, TOK / 128, 1), 256>>>(p_o, Wo, TOK, 64, 64, 0, 0, EpiWo{bo, tgt});
    // 7) LN(mid) -> g_lnT
    k_ln64<<<TOK / 8, 256>>>(nullptr, g2, bt2, 1);
    // 8) FFN in 4 chunks (hidden buffer reuses g_o)
    for (int c = 0; c < 4; c++) {
        int off = c * CHUNK;
        k_mma<<<dim3(DFF / 64, CHUNK / 128, 1), 256>>>(
            p_lnT + (size_t)off * 64, W1, CHUNK, DFF, 64, 0, 0, EpiW1{b1});
        k_mma<<<dim3(1, CHUNK / 128, 1), 256>>>(
            p_o, W2, CHUNK, 64, DFF, 0, 0, EpiW2{b2, out, off});
    }
}

// round 3
// speedup vs baseline: 2.3528x; 1.2883x over previous
#include <cuda_runtime.h>
#include <math.h>
#include <stdint.h>

#define LDIM 384
#define NSEQ 512
#define DIN 128
#define DOUT 64
#define HEADS 4
#define DFF 256
#define TOK (NSEQ*LDIM)      // 196608

// ---------------- scratch ----------------------------------------------------
__device__ float g_attn[HEADS*LDIM*LDIM];   // logits -> softmax
__device__ float g_v[TOK*DOUT];             // v transposed [h][n][c][k]
__device__ float g_o[TOK*DOUT];             // attention out [n][l][64]

__device__ __forceinline__ float warpSum(float v) {
#pragma unroll
    for (int o = 16; o > 0; o >>= 1) v += __shfl_xor_sync(0xffffffffu, v, o);
    return v;
}
__device__ __forceinline__ uint32_t f2tf(float f) {
    uint32_t u;
    asm("cvt.rna.tf32.f32 %0, %1;" : "=r"(u) : "f"(f));
    return u;
}
__device__ __forceinline__ void mma_tf32(
    float& c0, float& c1, float& c2, float& c3,
    uint32_t a0, uint32_t a1, uint32_t a2, uint32_t a3,
    uint32_t b0, uint32_t b1)
{
    asm volatile(
        "mma.sync.aligned.m16n8k8.row.col.f32.tf32.tf32.f32 "
        "{%0,%1,%2,%3},{%4,%5,%6,%7},{%8,%9},{%0,%1,%2,%3};"
        : "+f"(c0), "+f"(c1), "+f"(c2), "+f"(c3)
        : "r"(a0), "r"(a1), "r"(a2), "r"(a3), "r"(b0), "r"(b1));
}

// ---------------- kernel 1: symmetrize + LN128 + @Wp, k<=l only -------------
__global__ __launch_bounds__(256) void k_logits(
    const float* __restrict__ src, const float* __restrict__ Wp,
    const float* __restrict__ bp, const float* __restrict__ gn,
    const float* __restrict__ btn)
{
    int warp = (blockIdx.x * blockDim.x + threadIdx.x) >> 5;
    int lane = threadIdx.x & 31;
    if (warp >= LDIM * LDIM) return;
    int k = warp / LDIM, l = warp % LDIM;
    if (k > l) return;                       // symmetric: compute upper triangle

    float4 a = *(const float4*)(src + ((size_t)k * LDIM + l) * DIN + lane * 4);
    float4 b = *(const float4*)(src + ((size_t)l * LDIM + k) * DIN + lane * 4);
    float x0 = 0.5f * (a.x + b.x), x1 = 0.5f * (a.y + b.y);
    float x2 = 0.5f * (a.z + b.z), x3 = 0.5f * (a.w + b.w);

    float m = warpSum(x0 + x1 + x2 + x3) * (1.0f / 128.0f);
    float d0 = x0 - m, d1 = x1 - m, d2 = x2 - m, d3 = x3 - m;
    float var = warpSum(d0*d0 + d1*d1 + d2*d2 + d3*d3) * (1.0f / 128.0f);
    float rinv = rsqrtf(var + 1e-5f);

    int i0 = lane * 4;
    float4 g  = *(const float4*)(gn  + i0);
    float4 bt = *(const float4*)(btn + i0);
    float y0 = g.x * d0 * rinv + bt.x;
    float y1 = g.y * d1 * rinv + bt.y;
    float y2 = g.z * d2 * rinv + bt.z;
    float y3 = g.w * d3 * rinv + bt.w;

    const float4* Wp4 = (const float4*)Wp;
    float4 w0 = Wp4[i0 + 0], w1 = Wp4[i0 + 1], w2 = Wp4[i0 + 2], w3 = Wp4[i0 + 3];

    float h0 = y0*w0.x + y1*w1.x + y2*w2.x + y3*w3.x;
    float h1 = y0*w0.y + y1*w1.y + y2*w2.y + y3*w3.y;
    float h2 = y0*w0.z + y1*w1.z + y2*w2.z + y3*w3.z;
    float h3 = y0*w0.w + y1*w1.w + y2*w2.w + y3*w3.w;
    h0 = warpSum(h0); h1 = warpSum(h1); h2 = warpSum(h2); h3 = warpSum(h3);

    if (lane == 0) {
        size_t p1 = (size_t)k * LDIM + l;
        size_t p2 = (size_t)l * LDIM + k;
        float v0 = h0 + bp[0], v1 = h1 + bp[1], v2 = h2 + bp[2], v3 = h3 + bp[3];
        g_attn[0 * LDIM * LDIM + p1] = v0; g_attn[0 * LDIM * LDIM + p2] = v0;
        g_attn[1 * LDIM * LDIM + p1] = v1; g_attn[1 * LDIM * LDIM + p2] = v1;
        g_attn[2 * LDIM * LDIM + p1] = v2; g_attn[2 * LDIM * LDIM + p2] = v2;
        g_attn[3 * LDIM * LDIM + p1] = v3; g_attn[3 * LDIM * LDIM + p2] = v3;
    }
}

// ---------------- kernel 2: softmax over k ----------------------------------
__global__ __launch_bounds__(128) void k_softmax()
{
    int h = blockIdx.x / LDIM;
    int l = blockIdx.x % LDIM;
    float* base = g_attn + (size_t)h * LDIM * LDIM + l;
    int t = threadIdx.x;

    float v0 = base[(size_t)(t      ) * LDIM];
    float v1 = base[(size_t)(t + 128) * LDIM];
    float v2 = base[(size_t)(t + 256) * LDIM];

    __shared__ float red[128];
    red[t] = fmaxf(v0, fmaxf(v1, v2));
    __syncthreads();
#pragma unroll
    for (int s = 64; s > 0; s >>= 1) {
        if (t < s) red[t] = fmaxf(red[t], red[t + s]);
        __syncthreads();
    }
    float mx = red[0];
    __syncthreads();

    float e0 = __expf(v0 - mx), e1 = __expf(v1 - mx), e2 = __expf(v2 - mx);
    red[t] = e0 + e1 + e2;
    __syncthreads();
#pragma unroll
    for (int s = 64; s > 0; s >>= 1) {
        if (t < s) red[t] += red[t + s];
        __syncthreads();
    }
    float rs = 1.0f / red[0];

    base[(size_t)(t      ) * LDIM] = e0 * rs;
    base[(size_t)(t + 128) * LDIM] = e1 * rs;
    base[(size_t)(t + 256) * LDIM] = e2 * rs;
}

// ---------------- kernel 3: fused LN(tgt) + @Wm + bm, scatter to g_v --------
// block = 64 rows, 256 threads (8 warps: 4m x 2n, warp tile 16x32)
__global__ __launch_bounds__(256) void k_vproj(
    const float* __restrict__ tgt, const float* __restrict__ Wm,
    const float* __restrict__ bm, const float* __restrict__ g1,
    const float* __restrict__ bt1)
{
    __shared__ uint32_t Aln[64 * 68];
    __shared__ uint32_t Bs[64 * 72];
    int r0 = blockIdx.x * 64;
    int tid = threadIdx.x, lane = tid & 31, wid = tid >> 5;
    int grp = lane >> 2, tig = lane & 3;

    // LN staging: warp wid handles rows wid*8 .. wid*8+7
#pragma unroll
    for (int rr = 0; rr < 8; rr++) {
        int row = wid * 8 + rr;
        float2 v = *(const float2*)(tgt + (size_t)(r0 + row) * 64 + lane * 2);
        float m = warpSum(v.x + v.y) * (1.0f / 64.0f);
        float d0 = v.x - m, d1 = v.y - m;
        float var = warpSum(d0*d0 + d1*d1) * (1.0f / 64.0f);
        float rinv = rsqrtf(var + 1e-5f);
        float2 gg = *(const float2*)(g1 + lane * 2);
        float2 bb = *(const float2*)(bt1 + lane * 2);
        Aln[row * 68 + lane * 2    ] = f2tf(gg.x * d0 * rinv + bb.x);
        Aln[row * 68 + lane * 2 + 1] = f2tf(gg.y * d1 * rinv + bb.y);
    }
    // stage Wm (64x64)
#pragma unroll
    for (int i = 0; i < 4; i++) {
        int idx4 = tid + i * 256;
        int row = idx4 >> 4, col4 = (idx4 & 15) * 4;
        float4 w = *(const float4*)(Wm + row * 64 + col4);
        uint32_t* d = &Bs[row * 72 + col4];
        d[0] = f2tf(w.x); d[1] = f2tf(w.y); d[2] = f2tf(w.z); d[3] = f2tf(w.w);
    }
    __syncthreads();

    int wm = wid >> 1, wn = wid & 1;
    float c[4][4] = {};
#pragma unroll
    for (int k0 = 0; k0 < 64; k0 += 8) {
        uint32_t a0 = Aln[(wm * 16 + grp    ) * 68 + k0 + tig];
        uint32_t a1 = Aln[(wm * 16 + grp + 8) * 68 + k0 + tig];
        uint32_t a2 = Aln[(wm * 16 + grp    ) * 68 + k0 + tig + 4];
        uint32_t a3 = Aln[(wm * 16 + grp + 8) * 68 + k0 + tig + 4];
#pragma unroll
        for (int nt = 0; nt < 4; nt++) {
            int bcol = wn * 32 + nt * 8 + grp;
            uint32_t b0 = Bs[(k0 + tig    ) * 72 + bcol];
            uint32_t b1 = Bs[(k0 + tig + 4) * 72 + bcol];
            mma_tf32(c[nt][0], c[nt][1], c[nt][2], c[nt][3], a0, a1, a2, a3, b0, b1);
        }
    }
    // scatter epilogue
#pragma unroll
    for (int nt = 0; nt < 4; nt++) {
        int col = wn * 32 + nt * 8 + 2 * tig;
#pragma unroll
        for (int q = 0; q < 4; q++) {
            int row = r0 + wm * 16 + grp + (q >= 2 ? 8 : 0);
            int cc  = col + (q & 1);
            float val = c[nt][q] + bm[cc];
            int n = row / LDIM, k = row % LDIM;
            g_v[(((size_t)(cc & 3) * NSEQ + n) * 16 + (cc >> 2)) * LDIM + k] = val;
        }
    }
}

// ---------------- kernel 4: per-head attn GEMM, 128x128 tile ----------------
__global__ __launch_bounds__(256) void k_attn()
{
    __shared__ uint32_t As[2][128 * 20];
    __shared__ uint32_t Bs[2][16 * 132];
    const float* A = g_v    + (size_t)blockIdx.z * (NSEQ * 16 * LDIM);
    const float* B = g_attn + (size_t)blockIdx.z * (LDIM * LDIM);
    int bm = blockIdx.y * 128, bn = blockIdx.x * 128;
    int tid = threadIdx.x, lane = tid & 31, wid = tid >> 5;
    int wm = wid >> 1, wn = wid & 1, grp = lane >> 2, tig = lane & 3;

    float c[2][8][4] = {};
    float4 ra[2], rb[2];

    // prologue k0=0
#pragma unroll
    for (int i = 0; i < 2; i++) {
        int idx4 = tid + i * 256;
        ra[i] = *(const float4*)(A + (size_t)(bm + (idx4 >> 2)) * LDIM + (idx4 & 3) * 4);
        rb[i] = *(const float4*)(B + (size_t)(idx4 >> 5) * LDIM + bn + (idx4 & 31) * 4);
    }
#pragma unroll
    for (int i = 0; i < 2; i++) {
        int idx4 = tid + i * 256;
        uint32_t* dA = &As[0][(idx4 >> 2) * 20 + (idx4 & 3) * 4];
        dA[0] = f2tf(ra[i].x); dA[1] = f2tf(ra[i].y); dA[2] = f2tf(ra[i].z); dA[3] = f2tf(ra[i].w);
        uint32_t* dB = &Bs[0][(idx4 >> 5) * 132 + (idx4 & 31) * 4];
        dB[0] = f2tf(rb[i].x); dB[1] = f2tf(rb[i].y); dB[2] = f2tf(rb[i].z); dB[3] = f2tf(rb[i].w);
    }
    __syncthreads();

    const int nstage = LDIM / 16;  // 24
    for (int s = 0; s < nstage; s++) {
        int buf = s & 1;
        bool more = (s + 1) < nstage;
        if (more) {
            int k0 = (s + 1) * 16;
#pragma unroll
            for (int i = 0; i < 2; i++) {
                int idx4 = tid + i * 256;
                ra[i] = *(const float4*)(A + (size_t)(bm + (idx4 >> 2)) * LDIM + k0 + (idx4 & 3) * 4);
                rb[i] = *(const float4*)(B + (size_t)(k0 + (idx4 >> 5)) * LDIM + bn + (idx4 & 31) * 4);
            }
        }
        const uint32_t* As_ = &As[buf][0];
        const uint32_t* Bs_ = &Bs[buf][0];
#pragma unroll
        for (int ks = 0; ks < 2; ks++) {
            uint32_t a[2][4], b[8][2];
#pragma unroll
            for (int mt = 0; mt < 2; mt++) {
                int arow = wm * 32 + mt * 16 + grp;
                int acol = ks * 8 + tig;
                a[mt][0] = As_[(arow    ) * 20 + acol];
                a[mt][1] = As_[(arow + 8) * 20 + acol];
                a[mt][2] = As_[(arow    ) * 20 + acol + 4];
                a[mt][3] = As_[(arow + 8) * 20 + acol + 4];
            }
#pragma unroll
            for (int nt = 0; nt < 8; nt++) {
                int bcol = wn * 64 + nt * 8 + grp;
                b[nt][0] = Bs_[(ks * 8 + tig    ) * 132 + bcol];
                b[nt][1] = Bs_[(ks * 8 + tig + 4) * 132 + bcol];
            }
#pragma unroll
            for (int mt = 0; mt < 2; mt++)
#pragma unroll
                for (int nt = 0; nt < 8; nt++)
                    mma_tf32(c[mt][nt][0], c[mt][nt][1], c[mt][nt][2], c[mt][nt][3],
                             a[mt][0], a[mt][1], a[mt][2], a[mt][3], b[nt][0], b[nt][1]);
        }
        if (more) {
            int nbuf = buf ^ 1;
#pragma unroll
            for (int i = 0; i < 2; i++) {
                int idx4 = tid + i * 256;
                uint32_t* dA = &As[nbuf][(idx4 >> 2) * 20 + (idx4 & 3) * 4];
                dA[0] = f2tf(ra[i].x); dA[1] = f2tf(ra[i].y); dA[2] = f2tf(ra[i].z); dA[3] = f2tf(ra[i].w);
                uint32_t* dB = &Bs[nbuf][(idx4 >> 5) * 132 + (idx4 & 31) * 4];
                dB[0] = f2tf(rb[i].x); dB[1] = f2tf(rb[i].y); dB[2] = f2tf(rb[i].z); dB[3] = f2tf(rb[i].w);
            }
        }
        __syncthreads();
    }
    // epilogue: scatter o[n][l][c*4+h]
    int h = blockIdx.z;
#pragma unroll
    for (int mt = 0; mt < 2; mt++)
#pragma unroll
        for (int nt = 0; nt < 8; nt++) {
#pragma unroll
            for (int q = 0; q < 4; q++) {
                int row = bm + wm * 32 + mt * 16 + grp + (q >= 2 ? 8 : 0);
                int col = bn + wn * 64 + nt * 8 + 2 * tig + (q & 1);
                int n = row >> 4, cc = row & 15;
                g_o[((size_t)n * LDIM + col) * 64 + cc * 4 + h] = c[mt][nt][q];
            }
        }
}

// ---------------- kernel 5: mega-tail ----------------------------------------
// per 64-row tile: mid = g_o@Wo + bo + tgt; LN(mid); h=relu(LN@W1+b1);
// out = mid + h@W2 + b2.   Dynamic smem 163.5KB.
#define SM_RAW   0                       // float[64*66]   (16896 B)
#define SM_HS    16896                   // u32 [64*260]   (66560 B)
#define SM_UNION 83456                   // Aln u32[64*68] then W1s u32[64*260]; or W2s u32[256*68]
#define SM_W1    (83456 + 17408)
#define SMEM_TAIL (83456 + 17408 + 66560)   // 167424

__global__ __launch_bounds__(256) void k_tail(
    const float* __restrict__ tgt,
    const float* __restrict__ Wo, const float* __restrict__ bo,
    const float* __restrict__ W1, const float* __restrict__ b1,
    const float* __restrict__ W2, const float* __restrict__ b2,
    const float* __restrict__ g2, const float* __restrict__ bt2,
    float* __restrict__ out)
{
    extern __shared__ char smem[];
    float*    raw = (float*)(smem + SM_RAW);        // mid tile [64][66]
    uint32_t* Hs  = (uint32_t*)(smem + SM_HS);      // hidden [64][260]
    uint32_t* Aln = (uint32_t*)(smem + SM_UNION);   // [64][68] (also A0 in phase 0)
    uint32_t* W1s = (uint32_t*)(smem + SM_W1);      // [64][260] (also Wo in phase 0)
    uint32_t* W2s = (uint32_t*)(smem + SM_UNION);   // [256][68]

    int r0 = blockIdx.x * 64;
    int tid = threadIdx.x, lane = tid & 31, wid = tid >> 5;
    int grp = lane >> 2, tig = lane & 3;

    // ---- phase 0: stage A0 = g_o tile, Wo ----
#pragma unroll
    for (int i = 0; i < 4; i++) {
        int idx4 = tid + i * 256;
        int row = idx4 >> 4, col4 = (idx4 & 15) * 4;
        float4 v = *(const float4*)(g_o + (size_t)(r0 + row) * 64 + col4);
        uint32_t* d = &Aln[row * 68 + col4];
        d[0] = f2tf(v.x); d[1] = f2tf(v.y); d[2] = f2tf(v.z); d[3] = f2tf(v.w);
        float4 w = *(const float4*)(Wo + row * 64 + col4);
        uint32_t* dw = &W1s[row * 72 + col4];  // temp Wo storage, stride 72 fits in W1s region
        dw[0] = f2tf(w.x); dw[1] = f2tf(w.y); dw[2] = f2tf(w.z); dw[3] = f2tf(w.w);
    }
    __syncthreads();

    // GEMM0: mid_pre = A0 @ Wo   (4m x 2n warps, warp tile 16x32)
    {
        int wm = wid >> 1, wn = wid & 1;
        float c[4][4] = {};
#pragma unroll
        for (int k0 = 0; k0 < 64; k0 += 8) {
            uint32_t a0 = Aln[(wm * 16 + grp    ) * 68 + k0 + tig];
            uint32_t a1 = Aln[(wm * 16 + grp + 8) * 68 + k0 + tig];
            uint32_t a2 = Aln[(wm * 16 + grp    ) * 68 + k0 + tig + 4];
            uint32_t a3 = Aln[(wm * 16 + grp + 8) * 68 + k0 + tig + 4];
#pragma unroll
            for (int nt = 0; nt < 4; nt++) {
                int bcol = wn * 32 + nt * 8 + grp;
                uint32_t b0 = W1s[(k0 + tig    ) * 72 + bcol];
                uint32_t b1v = W1s[(k0 + tig + 4) * 72 + bcol];
                mma_tf32(c[nt][0], c[nt][1], c[nt][2], c[nt][3], a0, a1, a2, a3, b0, b1v);
            }
        }
        __syncthreads();   // done reading A0/Wo before raw writes race? raw is separate; sync protects later overwrite
        // mid = c + bo + tgt -> raw
#pragma unroll
        for (int nt = 0; nt < 4; nt++) {
            int col = wn * 32 + nt * 8 + 2 * tig;
#pragma unroll
            for (int q = 0; q < 4; q++) {
                int lrow = wm * 16 + grp + (q >= 2 ? 8 : 0);
                int cc = col + (q & 1);
                raw[lrow * 66 + cc] = c[nt][q] + bo[cc]
                                    + tgt[(size_t)(r0 + lrow) * 64 + cc];
            }
        }
    }
    __syncthreads();

    // ---- phase 1: LN(raw) -> Aln; stage W1 ----
#pragma unroll
    for (int rr = 0; rr < 8; rr++) {
        int row = wid * 8 + rr;
        float x0 = raw[row * 66 + lane * 2];
        float x1 = raw[row * 66 + lane * 2 + 1];
        float m = warpSum(x0 + x1) * (1.0f / 64.0f);
        float d0 = x0 - m, d1 = x1 - m;
        float var = warpSum(d0*d0 + d1*d1) * (1.0f / 64.0f);
        float rinv = rsqrtf(var + 1e-5f);
        float2 gg = *(const float2*)(g2 + lane * 2);
        float2 bb = *(const float2*)(bt2 + lane * 2);
        Aln[row * 68 + lane * 2    ] = f2tf(gg.x * d0 * rinv + bb.x);
        Aln[row * 68 + lane * 2 + 1] = f2tf(gg.y * d1 * rinv + bb.y);
    }
#pragma unroll
    for (int i = 0; i < 16; i++) {
        int idx4 = tid + i * 256;
        int row = idx4 >> 6, col4 = (idx4 & 63) * 4;
        float4 w = *(const float4*)(W1 + row * DFF + col4);
        uint32_t* d = &W1s[row * 260 + col4];
        d[0] = f2tf(w.x); d[1] = f2tf(w.y); d[2] = f2tf(w.z); d[3] = f2tf(w.w);
    }
    __syncthreads();

    // ---- GEMM1: hidden = relu(Aln @ W1 + b1)  (2m x 4n, warp tile 32x64) ----
    {
        int wm = wid >> 2, wn = wid & 3;
        float c[2][8][4] = {};
#pragma unroll
        for (int k0 = 0; k0 < 64; k0 += 8) {
            uint32_t a[2][4];
#pragma unroll
            for (int mt = 0; mt < 2; mt++) {
                int arow = wm * 32 + mt * 16 + grp;
                a[mt][0] = Aln[(arow    ) * 68 + k0 + tig];
                a[mt][1] = Aln[(arow + 8) * 68 + k0 + tig];
                a[mt][2] = Aln[(arow    ) * 68 + k0 + tig + 4];
                a[mt][3] = Aln[(arow + 8) * 68 + k0 + tig + 4];
            }
#pragma unroll
            for (int nt = 0; nt < 8; nt++) {
                int bcol = wn * 64 + nt * 8 + grp;
                uint32_t b0 = W1s[(k0 + tig    ) * 260 + bcol];
                uint32_t b1v = W1s[(k0 + tig + 4) * 260 + bcol];
#pragma unroll
                for (int mt = 0; mt < 2; mt++)
                    mma_tf32(c[mt][nt][0], c[mt][nt][1], c[mt][nt][2], c[mt][nt][3],
                             a[mt][0], a[mt][1], a[mt][2], a[mt][3], b0, b1v);
            }
        }
        // relu + store hidden
#pragma unroll
        for (int mt = 0; mt < 2; mt++)
#pragma unroll
            for (int nt = 0; nt < 8; nt++) {
                int row = wm * 32 + mt * 16 + grp;
                int col = wn * 64 + nt * 8 + 2 * tig;
                Hs[(row    ) * 260 + col    ] = f2tf(fmaxf(c[mt][nt][0] + b1[col    ], 0.f));
                Hs[(row    ) * 260 + col + 1] = f2tf(fmaxf(c[mt][nt][1] + b1[col + 1], 0.f));
                Hs[(row + 8) * 260 + col    ] = f2tf(fmaxf(c[mt][nt][2] + b1[col    ], 0.f));
                Hs[(row + 8) * 260 + col + 1] = f2tf(fmaxf(c[mt][nt][3] + b1[col + 1], 0.f));
            }
    }
    __syncthreads();

    // ---- phase 2: stage W2 (overwrites Aln/W1s) ----
#pragma unroll
    for (int i = 0; i < 16; i++) {
        int idx4 = tid + i * 256;
        int row = idx4 >> 4, col4 = (idx4 & 15) * 4;
        float4 w = *(const float4*)(W2 + row * 64 + col4);
        uint32_t* d = &W2s[row * 68 + col4];
        d[0] = f2tf(w.x); d[1] = f2tf(w.y); d[2] = f2tf(w.z); d[3] = f2tf(w.w);
    }
    __syncthreads();

    // ---- GEMM2: out = Hs @ W2 + b2 + raw  (4m x 2n, warp tile 16x32) ----
    {
        int wm = wid >> 1, wn = wid & 1;
        float c[4][4] = {};
#pragma unroll 8
        for (int k0 = 0; k0 < 256; k0 += 8) {
            uint32_t a0 = Hs[(wm * 16 + grp    ) * 260 + k0 + tig];
            uint32_t a1 = Hs[(wm * 16 + grp + 8) * 260 + k0 + tig];
            uint32_t a2 = Hs[(wm * 16 + grp    ) * 260 + k0 + tig + 4];
            uint32_t a3 = Hs[(wm * 16 + grp + 8) * 260 + k0 + tig + 4];
#pragma unroll
            for (int nt = 0; nt < 4; nt++) {
                int bcol = wn * 32 + nt * 8 + grp;
                uint32_t b0 = W2s[(k0 + tig    ) * 68 + bcol];
                uint32_t b1v = W2s[(k0 + tig + 4) * 68 + bcol];
                mma_tf32(c[nt][0], c[nt][1], c[nt][2], c[nt][3], a0, a1, a2, a3, b0, b1v);
            }
        }
#pragma unroll
        for (int nt = 0; nt < 4; nt++) {
            int col = wn * 32 + nt * 8 + 2 * tig;
#pragma unroll
            for (int q = 0; q < 4; q++) {
                int lrow = wm * 16 + grp + (q >= 2 ? 8 : 0);
                int cc = col + (q & 1);
                out[(size_t)(r0 + lrow) * 64 + cc] =
                    c[nt][q] + b2[cc] + raw[lrow * 66 + cc];
            }
        }
    }
}

// ---------------- launch ------------------------------------------------------
extern "C" void kernel_launch(void* const* d_in, const int* in_sizes, int n_in,
                              void* d_out, int out_size)
{
    const float* src = (const float*)d_in[0];
    const float* tgt = (const float*)d_in[1];
    const float* Wp  = (const float*)d_in[2];
    const float* bp  = (const float*)d_in[3];
    const float* Wm  = (const float*)d_in[4];
    const float* bm  = (const float*)d_in[5];
    const float* Wo  = (const float*)d_in[6];
    const float* bo  = (const float*)d_in[7];
    const float* W1  = (const float*)d_in[8];
    const float* b1  = (const float*)d_in[9];
    const float* W2  = (const float*)d_in[10];
    const float* b2  = (const float*)d_in[11];
    const float* gn  = (const float*)d_in[12];
    const float* btn = (const float*)d_in[13];
    const float* g1  = (const float*)d_in[14];
    const float* bt1 = (const float*)d_in[15];
    const float* g2  = (const float*)d_in[16];
    const float* bt2 = (const float*)d_in[17];
    float* out = (float*)d_out;

    cudaFuncSetAttribute(k_tail, cudaFuncAttributeMaxDynamicSharedMemorySize, SMEM_TAIL);

    // 1) pair logits (symmetric half)
    k_logits<<<(LDIM * LDIM) / 8, 256>>>(src, Wp, bp, gn, btn);
    // 2) softmax over k
    k_softmax<<<HEADS * LDIM, 128>>>();
    // 3) fused LN + v projection (scatter to [h][n][c][k])
    k_vproj<<<TOK / 64, 256>>>(tgt, Wm, bm, g1, bt1);
    // 4) per-head attention GEMM (128x128 tiles)
    k_attn<<<dim3(LDIM / 128, (NSEQ * 16) / 128, HEADS), 256>>>();
    // 5) fused Wo + residual + LN + FFN + residual
    k_tail<<<TOK / 64, 256, SMEM_TAIL>>>(tgt, Wo, bo, W1, b1, W2, b2, g2, bt2, out);
}

// round 4
// speedup vs baseline: 3.9955x; 1.6982x over previous
#include <cuda_runtime.h>
#include <cuda_fp16.h>
#include <math.h>
#include <stdint.h>

#define LDIM 384
#define NSEQ 512
#define DIN 128
#define HEADS 4
#define DFF 256
#define TOK (NSEQ*LDIM)      // 196608

// ---------------- scratch -----------------------------------------------------
__device__ __align__(256) float  g_attn [HEADS*LDIM*LDIM];   // symmetric logits
__device__ __align__(256) __half g_attnh[HEADS*LDIM*LDIM];   // softmax [h][l][k]
__device__ __align__(256) __half g_vh   [HEADS*NSEQ*16*LDIM];// v [h][(n,c)][k]
__device__ __align__(256) __half g_oh   [TOK*64];            // o [token][h*16+c]

__device__ __forceinline__ float warpSum(float v) {
#pragma unroll
    for (int o = 16; o > 0; o >>= 1) v += __shfl_xor_sync(0xffffffffu, v, o);
    return v;
}
__device__ __forceinline__ uint32_t f2tf(float f) {
    uint32_t u;
    asm("cvt.rna.tf32.f32 %0, %1;" : "=r"(u) : "f"(f));
    return u;
}
__device__ __forceinline__ void mma_tf32(
    float& c0, float& c1, float& c2, float& c3,
    uint32_t a0, uint32_t a1, uint32_t a2, uint32_t a3,
    uint32_t b0, uint32_t b1)
{
    asm volatile(
        "mma.sync.aligned.m16n8k8.row.col.f32.tf32.tf32.f32 "
        "{%0,%1,%2,%3},{%4,%5,%6,%7},{%8,%9},{%0,%1,%2,%3};"
        : "+f"(c0), "+f"(c1), "+f"(c2), "+f"(c3)
        : "r"(a0), "r"(a1), "r"(a2), "r"(a3), "r"(b0), "r"(b1));
}
__device__ __forceinline__ void mma_f16(float* c, const uint32_t* a, const uint32_t* b) {
    asm volatile(
        "mma.sync.aligned.m16n8k16.row.col.f32.f16.f16.f32 "
        "{%0,%1,%2,%3},{%4,%5,%6,%7},{%8,%9},{%0,%1,%2,%3};"
        : "+f"(c[0]), "+f"(c[1]), "+f"(c[2]), "+f"(c[3])
        : "r"(a[0]), "r"(a[1]), "r"(a[2]), "r"(a[3]), "r"(b[0]), "r"(b[1]));
}
__device__ __forceinline__ uint32_t s2u(const void* p) {
    uint32_t a;
    asm("{ .reg .u64 t; cvta.to.shared.u64 t, %1; cvt.u32.u64 %0, t; }"
        : "=r"(a) : "l"(p));
    return a;
}
__device__ __forceinline__ void ldmx2t(uint32_t& b0, uint32_t& b1, uint32_t addr) {
    asm volatile("ldmatrix.sync.aligned.m8n8.x2.trans.shared.b16 {%0,%1}, [%2];"
                 : "=r"(b0), "=r"(b1) : "r"(addr));
}
__device__ __forceinline__ void cp16(uint32_t dst, const void* src) {
    asm volatile("cp.async.ca.shared.global [%0], [%1], 16;" :: "r"(dst), "l"(src));
}

// ---------------- kernel 1: symmetrize + LN128 + @Wp, k<=l, write both ------
__global__ __launch_bounds__(256) void k_logits(
    const float* __restrict__ src, const float* __restrict__ Wp,
    const float* __restrict__ bp, const float* __restrict__ gn,
    const float* __restrict__ btn)
{
    int warp = (blockIdx.x * blockDim.x + threadIdx.x) >> 5;
    int lane = threadIdx.x & 31;
    if (warp >= LDIM * LDIM) return;
    int k = warp / LDIM, l = warp % LDIM;
    if (k > l) return;

    float4 a = *(const float4*)(src + ((size_t)k * LDIM + l) * DIN + lane * 4);
    float4 b = *(const float4*)(src + ((size_t)l * LDIM + k) * DIN + lane * 4);
    float x0 = 0.5f * (a.x + b.x), x1 = 0.5f * (a.y + b.y);
    float x2 = 0.5f * (a.z + b.z), x3 = 0.5f * (a.w + b.w);

    float m = warpSum(x0 + x1 + x2 + x3) * (1.0f / 128.0f);
    float d0 = x0 - m, d1 = x1 - m, d2 = x2 - m, d3 = x3 - m;
    float var = warpSum(d0*d0 + d1*d1 + d2*d2 + d3*d3) * (1.0f / 128.0f);
    float rinv = rsqrtf(var + 1e-5f);

    int i0 = lane * 4;
    float4 g  = *(const float4*)(gn  + i0);
    float4 bt = *(const float4*)(btn + i0);
    float y0 = g.x * d0 * rinv + bt.x;
    float y1 = g.y * d1 * rinv + bt.y;
    float y2 = g.z * d2 * rinv + bt.z;
    float y3 = g.w * d3 * rinv + bt.w;

    const float4* Wp4 = (const float4*)Wp;
    float4 w0 = Wp4[i0 + 0], w1 = Wp4[i0 + 1], w2 = Wp4[i0 + 2], w3 = Wp4[i0 + 3];

    float h0 = y0*w0.x + y1*w1.x + y2*w2.x + y3*w3.x;
    float h1 = y0*w0.y + y1*w1.y + y2*w2.y + y3*w3.y;
    float h2 = y0*w0.z + y1*w1.z + y2*w2.z + y3*w3.z;
    float h3 = y0*w0.w + y1*w1.w + y2*w2.w + y3*w3.w;
    h0 = warpSum(h0); h1 = warpSum(h1); h2 = warpSum(h2); h3 = warpSum(h3);

    if (lane == 0) {
        size_t p1 = (size_t)k * LDIM + l;
        size_t p2 = (size_t)l * LDIM + k;
        float v0 = h0 + bp[0], v1 = h1 + bp[1], v2 = h2 + bp[2], v3 = h3 + bp[3];
        g_attn[0 * LDIM * LDIM + p1] = v0; g_attn[0 * LDIM * LDIM + p2] = v0;
        g_attn[1 * LDIM * LDIM + p1] = v1; g_attn[1 * LDIM * LDIM + p2] = v1;
        g_attn[2 * LDIM * LDIM + p1] = v2; g_attn[2 * LDIM * LDIM + p2] = v2;
        g_attn[3 * LDIM * LDIM + p1] = v3; g_attn[3 * LDIM * LDIM + p2] = v3;
    }
}

// ---------------- kernel 2: softmax over k; logits symmetric so read ROW l --
// write half, layout [h][l][k] (transposed = what the attn GEMM wants)
__global__ __launch_bounds__(128) void k_softmax()
{
    int h = blockIdx.x / LDIM;
    int l = blockIdx.x % LDIM;
    const float* p = g_attn + ((size_t)h * LDIM + l) * LDIM;
    __half* q = g_attnh + ((size_t)h * LDIM + l) * LDIM;
    int t = threadIdx.x;

    float v0 = p[t], v1 = p[t + 128], v2 = p[t + 256];

    __shared__ float red[128];
    red[t] = fmaxf(v0, fmaxf(v1, v2));
    __syncthreads();
#pragma unroll
    for (int s = 64; s > 0; s >>= 1) {
        if (t < s) red[t] = fmaxf(red[t], red[t + s]);
        __syncthreads();
    }
    float mx = red[0];
    __syncthreads();

    float e0 = __expf(v0 - mx), e1 = __expf(v1 - mx), e2 = __expf(v2 - mx);
    red[t] = e0 + e1 + e2;
    __syncthreads();
#pragma unroll
    for (int s = 64; s > 0; s >>= 1) {
        if (t < s) red[t] += red[t + s];
        __syncthreads();
    }
    float rs = 1.0f / red[0];

    q[t      ] = __float2half_rn(e0 * rs);
    q[t + 128] = __float2half_rn(e1 * rs);
    q[t + 256] = __float2half_rn(e2 * rs);
}

// ---------------- kernel 3: fused LN(tgt) + @Wm + bm -> g_vh (half) ---------
__global__ __launch_bounds__(256) void k_vproj(
    const float* __restrict__ tgt, const float* __restrict__ Wm,
    const float* __restrict__ bm, const float* __restrict__ g1,
    const float* __restrict__ bt1)
{
    __shared__ uint32_t Aln[64 * 68];
    __shared__ uint32_t Bs[64 * 72];
    int r0 = blockIdx.x * 64;
    int tid = threadIdx.x, lane = tid & 31, wid = tid >> 5;
    int grp = lane >> 2, tig = lane & 3;

#pragma unroll
    for (int rr = 0; rr < 8; rr++) {
        int row = wid * 8 + rr;
        float2 v = *(const float2*)(tgt + (size_t)(r0 + row) * 64 + lane * 2);
        float m = warpSum(v.x + v.y) * (1.0f / 64.0f);
        float d0 = v.x - m, d1 = v.y - m;
        float var = warpSum(d0*d0 + d1*d1) * (1.0f / 64.0f);
        float rinv = rsqrtf(var + 1e-5f);
        float2 gg = *(const float2*)(g1 + lane * 2);
        float2 bb = *(const float2*)(bt1 + lane * 2);
        Aln[row * 68 + lane * 2    ] = f2tf(gg.x * d0 * rinv + bb.x);
        Aln[row * 68 + lane * 2 + 1] = f2tf(gg.y * d1 * rinv + bb.y);
    }
#pragma unroll
    for (int i = 0; i < 4; i++) {
        int idx4 = tid + i * 256;
        int row = idx4 >> 4, col4 = (idx4 & 15) * 4;
        float4 w = *(const float4*)(Wm + row * 64 + col4);
        uint32_t* d = &Bs[row * 72 + col4];
        d[0] = f2tf(w.x); d[1] = f2tf(w.y); d[2] = f2tf(w.z); d[3] = f2tf(w.w);
    }
    __syncthreads();

    int wm = wid >> 1, wn = wid & 1;
    float c[4][4] = {};
#pragma unroll
    for (int k0 = 0; k0 < 64; k0 += 8) {
        uint32_t a0 = Aln[(wm * 16 + grp    ) * 68 + k0 + tig];
        uint32_t a1 = Aln[(wm * 16 + grp + 8) * 68 + k0 + tig];
        uint32_t a2 = Aln[(wm * 16 + grp    ) * 68 + k0 + tig + 4];
        uint32_t a3 = Aln[(wm * 16 + grp + 8) * 68 + k0 + tig + 4];
#pragma unroll
        for (int nt = 0; nt < 4; nt++) {
            int bcol = wn * 32 + nt * 8 + grp;
            uint32_t b0 = Bs[(k0 + tig    ) * 72 + bcol];
            uint32_t b1 = Bs[(k0 + tig + 4) * 72 + bcol];
            mma_tf32(c[nt][0], c[nt][1], c[nt][2], c[nt][3], a0, a1, a2, a3, b0, b1);
        }
    }
#pragma unroll
    for (int nt = 0; nt < 4; nt++) {
        int col = wn * 32 + nt * 8 + 2 * tig;
#pragma unroll
        for (int q = 0; q < 4; q++) {
            int row = r0 + wm * 16 + grp + (q >= 2 ? 8 : 0);
            int cc  = col + (q & 1);
            float val = c[nt][q] + bm[cc];
            int n = row / LDIM, k = row % LDIM;
            g_vh[(((size_t)(cc & 3) * NSEQ + n) * 16 + (cc >> 2)) * LDIM + k] =
                __float2half_rn(val);
        }
    }
}

// ---------------- kernel 4: per-head attn GEMM fp16, cp.async 4-stage -------
// A = g_vh [m=(n,c)][k], B = g_attnh [l][k].  Tile 128x128, BK=32.
#define KA_ST 40           // halves per smem row (32 + 8 pad)
#define KA_STAGE (128*KA_ST)
__global__ __launch_bounds__(256, 2) void k_attn()
{
    extern __shared__ __half sm[];
    __half* As = sm;                       // [4][128*40]
    __half* Bs = sm + 4 * KA_STAGE;
    const __half* A = g_vh    + (size_t)blockIdx.z * (NSEQ * 16 * LDIM);
    const __half* B = g_attnh + (size_t)blockIdx.z * (LDIM * LDIM);
    int bm = blockIdx.y * 128, bn = blockIdx.x * 128;
    int tid = threadIdx.x, lane = tid & 31, wid = tid >> 5;
    int wm = wid >> 2, wn = wid & 3, grp = lane >> 2, tig = lane & 3;
    uint32_t sA = s2u(As), sB = s2u(Bs);

    int crow = tid >> 2, cch = (tid & 3) * 8;       // staging: row, half-offset
    int crow2 = (tid + 256) >> 2, cch2 = ((tid + 256) & 3) * 8;

    float c[4][4][4] = {};

    // prologue: stages 0..2
#pragma unroll
    for (int p = 0; p < 3; p++) {
        int k0 = p * 32;
        cp16(sA + (p * KA_STAGE + crow  * KA_ST + cch ) * 2, A + (size_t)(bm + crow ) * LDIM + k0 + cch );
        cp16(sA + (p * KA_STAGE + crow2 * KA_ST + cch2) * 2, A + (size_t)(bm + crow2) * LDIM + k0 + cch2);
        cp16(sB + (p * KA_STAGE + crow  * KA_ST + cch ) * 2, B + (size_t)(bn + crow ) * LDIM + k0 + cch );
        cp16(sB + (p * KA_STAGE + crow2 * KA_ST + cch2) * 2, B + (size_t)(bn + crow2) * LDIM + k0 + cch2);
        asm volatile("cp.async.commit_group;");
    }

    for (int s = 0; s < 12; s++) {
        asm volatile("cp.async.wait_group 2;");
        __syncthreads();
        if (s + 3 < 12) {
            int buf = (s + 3) & 3, k0 = (s + 3) * 32;
            cp16(sA + (buf * KA_STAGE + crow  * KA_ST + cch ) * 2, A + (size_t)(bm + crow ) * LDIM + k0 + cch );
            cp16(sA + (buf * KA_STAGE + crow2 * KA_ST + cch2) * 2, A + (size_t)(bm + crow2) * LDIM + k0 + cch2);
            cp16(sB + (buf * KA_STAGE + crow  * KA_ST + cch ) * 2, B + (size_t)(bn + crow ) * LDIM + k0 + cch );
            cp16(sB + (buf * KA_STAGE + crow2 * KA_ST + cch2) * 2, B + (size_t)(bn + crow2) * LDIM + k0 + cch2);
        }
        asm volatile("cp.async.commit_group;");

        const uint32_t* Au = (const uint32_t*)(As + (s & 3) * KA_STAGE);
        const uint32_t* Bu = (const uint32_t*)(Bs + (s & 3) * KA_STAGE);
#pragma unroll
        for (int ks = 0; ks < 2; ks++) {
            uint32_t a[4][4], b[4][2];
#pragma unroll
            for (int mt = 0; mt < 4; mt++) {
                int r = wm * 64 + mt * 16 + grp;
                a[mt][0] = Au[(r    ) * 20 + ks * 8 + tig];
                a[mt][1] = Au[(r + 8) * 20 + ks * 8 + tig];
                a[mt][2] = Au[(r    ) * 20 + ks * 8 + tig + 4];
                a[mt][3] = Au[(r + 8) * 20 + ks * 8 + tig + 4];
            }
#pragma unroll
            for (int nt = 0; nt < 4; nt++) {
                int n = wn * 32 + nt * 8 + grp;
                b[nt][0] = Bu[n * 20 + ks * 8 + tig];
                b[nt][1] = Bu[n * 20 + ks * 8 + tig + 4];
            }
#pragma unroll
            for (int mt = 0; mt < 4; mt++)
#pragma unroll
                for (int nt = 0; nt < 4; nt++)
                    mma_f16(c[mt][nt], a[mt], b[nt]);
        }
    }

    int h = blockIdx.z;
#pragma unroll
    for (int mt = 0; mt < 4; mt++)
#pragma unroll
        for (int nt = 0; nt < 4; nt++)
#pragma unroll
            for (int q = 0; q < 4; q++) {
                int row = bm + wm * 64 + mt * 16 + grp + ((q >= 2) ? 8 : 0);
                int col = bn + wn * 32 + nt * 8 + 2 * tig + (q & 1);
                int n = row >> 4, cc = row & 15;
                g_oh[((size_t)n * LDIM + col) * 64 + h * 16 + cc] =
                    __float2half_rn(c[mt][nt][q]);
            }
}

// ---------------- kernel 5: fused tail, fp16 mma ----------------------------
// regions: raw f32[64][66] | Ah half[64][72] | Hs half[64][264] | Ws (max 36864B)
#define T_RAW 0
#define T_A   16896
#define T_HS  26112
#define T_W   59904
#define SMEM_TAIL 96768

__global__ __launch_bounds__(256, 2) void k_tail(
    const float* __restrict__ tgt,
    const float* __restrict__ Wo, const float* __restrict__ bo,
    const float* __restrict__ W1, const float* __restrict__ b1,
    const float* __restrict__ W2, const float* __restrict__ b2,
    const float* __restrict__ g2, const float* __restrict__ bt2,
    float* __restrict__ out)
{
    extern __shared__ char smem[];
    float*   raw = (float*)(smem + T_RAW);
    __half*  Ah  = (__half*)(smem + T_A);
    __half*  Ws  = (__half*)(smem + T_W);
    uint32_t* AhU = (uint32_t*)Ah;
    uint32_t* HsU = (uint32_t*)(smem + T_HS);
    __half2*  Ws2 = (__half2*)Ws;
    __half2*  Hs2 = (__half2*)(smem + T_HS);
    __half2*  Ah2 = (__half2*)Ah;
    uint32_t sWs = s2u(Ws);

    int r0 = blockIdx.x * 64;
    int tid = threadIdx.x, lane = tid & 31, wid = tid >> 5;
    int grp = lane >> 2, tig = lane & 3;
    int lk = lane & 15;

    // ---- phase 0 staging: A0 <- g_oh tile (already half, permuted channels);
    //      Ws0 <- Wo with matching row permutation kp = (k%4)*16 + k/4
#pragma unroll
    for (int i = 0; i < 2; i++) {
        int idx = tid + i * 256;
        int row = idx >> 3, ch = (idx & 7) * 8;
        *(uint4*)(Ah + row * 72 + ch) = *(const uint4*)(g_oh + (size_t)(r0 + row) * 64 + ch);
    }
#pragma unroll
    for (int i = 0; i < 4; i++) {
        int idx = tid + i * 256;
        int k = idx >> 4, n4 = (idx & 15) * 4;
        float4 w = *(const float4*)(Wo + k * 64 + n4);
        int kp = (k & 3) * 16 + (k >> 2);
        Ws2[kp * 36 + n4 / 2    ] = __floats2half2_rn(w.x, w.y);
        Ws2[kp * 36 + n4 / 2 + 1] = __floats2half2_rn(w.z, w.w);
    }
    __syncthreads();

    // ---- GEMM0: mid = A0 @ Wo + bo + tgt -> raw  (warps 4m x 2n, 16x32) ----
    {
        int wm = wid >> 1, wn = wid & 1;
        int m0 = wm * 16, nb = wn * 32;
        float c[4][4] = {};
#pragma unroll
        for (int kw = 0; kw < 4; kw++) {
            uint32_t a[4];
            a[0] = AhU[(m0 + grp    ) * 36 + kw * 8 + tig];
            a[1] = AhU[(m0 + grp + 8) * 36 + kw * 8 + tig];
            a[2] = AhU[(m0 + grp    ) * 36 + kw * 8 + tig + 4];
            a[3] = AhU[(m0 + grp + 8) * 36 + kw * 8 + tig + 4];
#pragma unroll
            for (int nt = 0; nt < 4; nt++) {
                uint32_t b[2];
                ldmx2t(b[0], b[1], sWs + ((kw * 16 + lk) * 72 + nb + nt * 8) * 2);
                mma_f16(c[nt], a, b);
            }
        }
#pragma unroll
        for (int nt = 0; nt < 4; nt++)
#pragma unroll
            for (int q = 0; q < 4; q++) {
                int lrow = m0 + grp + ((q >= 2) ? 8 : 0);
                int cc = nb + nt * 8 + 2 * tig + (q & 1);
                raw[lrow * 66 + cc] = c[nt][q] + bo[cc] + tgt[(size_t)(r0 + lrow) * 64 + cc];
            }
    }
    __syncthreads();

    // ---- phase 1: LN(raw) -> Ah; stage W1 [64][256] -> Ws ----
#pragma unroll
    for (int rr = 0; rr < 8; rr++) {
        int row = wid * 8 + rr;
        float x0 = raw[row * 66 + lane * 2], x1 = raw[row * 66 + lane * 2 + 1];
        float m = warpSum(x0 + x1) * (1.0f / 64.0f);
        float d0 = x0 - m, d1 = x1 - m;
        float var = warpSum(d0*d0 + d1*d1) * (1.0f / 64.0f);
        float rinv = rsqrtf(var + 1e-5f);
        float2 gg = *(const float2*)(g2 + lane * 2);
        float2 bb = *(const float2*)(bt2 + lane * 2);
        Ah2[row * 36 + lane] = __floats2half2_rn(gg.x * d0 * rinv + bb.x,
                                                 gg.y * d1 * rinv + bb.y);
    }
#pragma unroll
    for (int i = 0; i < 16; i++) {
        int idx = tid + i * 256;
        int k = idx >> 6, n4 = (idx & 63) * 4;
        float4 w = *(const float4*)(W1 + k * DFF + n4);
        Ws2[k * 132 + n4 / 2    ] = __floats2half2_rn(w.x, w.y);
        Ws2[k * 132 + n4 / 2 + 1] = __floats2half2_rn(w.z, w.w);
    }
    __syncthreads();

    // ---- GEMM1: hidden = relu(Ah @ W1 + b1) -> Hs  (warps 2m x 4n, 32x64) --
    {
        int wm = wid >> 2, wn = wid & 3;
        float c[2][8][4] = {};
#pragma unroll
        for (int kw = 0; kw < 4; kw++) {
            uint32_t a[2][4];
#pragma unroll
            for (int mt = 0; mt < 2; mt++) {
                int r = wm * 32 + mt * 16 + grp;
                a[mt][0] = AhU[(r    ) * 36 + kw * 8 + tig];
                a[mt][1] = AhU[(r + 8) * 36 + kw * 8 + tig];
                a[mt][2] = AhU[(r    ) * 36 + kw * 8 + tig + 4];
                a[mt][3] = AhU[(r + 8) * 36 + kw * 8 + tig + 4];
            }
#pragma unroll
            for (int nt = 0; nt < 8; nt++) {
                uint32_t b[2];
                ldmx2t(b[0], b[1], sWs + ((kw * 16 + lk) * 264 + wn * 64 + nt * 8) * 2);
#pragma unroll
                for (int mt = 0; mt < 2; mt++) mma_f16(c[mt][nt], a[mt], b);
            }
        }
#pragma unroll
        for (int mt = 0; mt < 2; mt++)
#pragma unroll
            for (int nt = 0; nt < 8; nt++)
#pragma unroll
                for (int q2 = 0; q2 < 2; q2++) {
                    int row = wm * 32 + mt * 16 + grp + q2 * 8;
                    int col = wn * 64 + nt * 8 + 2 * tig;
                    float v0 = fmaxf(c[mt][nt][q2 * 2 + 0] + b1[col    ], 0.f);
                    float v1 = fmaxf(c[mt][nt][q2 * 2 + 1] + b1[col + 1], 0.f);
                    Hs2[row * 132 + col / 2] = __floats2half2_rn(v0, v1);
                }
    }
    __syncthreads();

    // ---- phase 2: stage W2 [256][64] -> Ws ----
#pragma unroll
    for (int i = 0; i < 16; i++) {
        int idx = tid + i * 256;
        int k = idx >> 4, n4 = (idx & 15) * 4;
        float4 w = *(const float4*)(W2 + k * 64 + n4);
        Ws2[k * 36 + n4 / 2    ] = __floats2half2_rn(w.x, w.y);
        Ws2[k * 36 + n4 / 2 + 1] = __floats2half2_rn(w.z, w.w);
    }
    __syncthreads();

    // ---- GEMM2: out = Hs @ W2 + b2 + raw  (warps 4m x 2n, 16x32) ----
    {
        int wm = wid >> 1, wn = wid & 1;
        int m0 = wm * 16, nb = wn * 32;
        float c[4][4] = {};
#pragma unroll
        for (int kw = 0; kw < 16; kw++) {
            uint32_t a[4];
            a[0] = HsU[(m0 + grp    ) * 132 + kw * 8 + tig];
            a[1] = HsU[(m0 + grp + 8) * 132 + kw * 8 + tig];
            a[2] = HsU[(m0 + grp    ) * 132 + kw * 8 + tig + 4];
            a[3] = HsU[(m0 + grp + 8) * 132 + kw * 8 + tig + 4];
#pragma unroll
            for (int nt = 0; nt < 4; nt++) {
                uint32_t b[2];
                ldmx2t(b[0], b[1], sWs + ((kw * 16 + lk) * 72 + nb + nt * 8) * 2);
                mma_f16(c[nt], a, b);
            }
        }
#pragma unroll
        for (int nt = 0; nt < 4; nt++)
#pragma unroll
            for (int q = 0; q < 4; q++) {
                int lrow = m0 + grp + ((q >= 2) ? 8 : 0);
                int cc = nb + nt * 8 + 2 * tig + (q & 1);
                out[(size_t)(r0 + lrow) * 64 + cc] = c[nt][q] + b2[cc] + raw[lrow * 66 + cc];
            }
    }
}

// ---------------- launch ------------------------------------------------------
extern "C" void kernel_launch(void* const* d_in, const int* in_sizes, int n_in,
                              void* d_out, int out_size)
{
    const float* src = (const float*)d_in[0];
    const float* tgt = (const float*)d_in[1];
    const float* Wp  = (const float*)d_in[2];
    const float* bp  = (const float*)d_in[3];
    const float* Wm  = (const float*)d_in[4];
    const float* bm  = (const float*)d_in[5];
    const float* Wo  = (const float*)d_in[6];
    const float* bo  = (const float*)d_in[7];
    const float* W1  = (const float*)d_in[8];
    const float* b1  = (const float*)d_in[9];
    const float* W2  = (const float*)d_in[10];
    const float* b2  = (const float*)d_in[11];
    const float* gn  = (const float*)d_in[12];
    const float* btn = (const float*)d_in[13];
    const float* g1  = (const float*)d_in[14];
    const float* bt1 = (const float*)d_in[15];
    const float* g2  = (const float*)d_in[16];
    const float* bt2 = (const float*)d_in[17];
    float* out = (float*)d_out;

    static int attr_done = 0;
    const int smem_attn = 4 * KA_STAGE * 2 * 2;   // 81920
    cudaFuncSetAttribute(k_attn, cudaFuncAttributeMaxDynamicSharedMemorySize, smem_attn);
    cudaFuncSetAttribute(k_tail, cudaFuncAttributeMaxDynamicSharedMemorySize, SMEM_TAIL);
    (void)attr_done;

    k_logits<<<(LDIM * LDIM) / 8, 256>>>(src, Wp, bp, gn, btn);
    k_softmax<<<HEADS * LDIM, 128>>>();
    k_vproj<<<TOK / 64, 256>>>(tgt, Wm, bm, g1, bt1);
    k_attn<<<dim3(LDIM / 128, (NSEQ * 16) / 128, HEADS), 256, smem_attn>>>();
    k_tail<<<TOK / 64, 256, SMEM_TAIL>>>(tgt, Wo, bo, W1, b1, W2, b2, g2, bt2, out);
}

// round 5
// speedup vs baseline: 4.2301x; 1.0587x over previous
#include <cuda_runtime.h>
#include <cuda_fp16.h>
#include <math.h>
#include <stdint.h>

#define LDIM 384
#define NSEQ 512
#define DIN 128
#define HEADS 4
#define DFF 256
#define TOK (NSEQ*LDIM)      // 196608

// ---------------- scratch -----------------------------------------------------
__device__ __align__(256) float  g_attn [HEADS*LDIM*LDIM];   // symmetric logits
__device__ __align__(256) __half g_attnh[HEADS*LDIM*LDIM];   // softmax [h][l][k]
__device__ __align__(256) __half g_vh   [HEADS*NSEQ*16*LDIM];// v [h][(n,c)][k]
__device__ __align__(256) __half g_oh   [TOK*64];            // o [token][h*16+c]

__device__ __forceinline__ float warpSum(float v) {
#pragma unroll
    for (int o = 16; o > 0; o >>= 1) v += __shfl_xor_sync(0xffffffffu, v, o);
    return v;
}
__device__ __forceinline__ uint32_t f2tf(float f) {
    uint32_t u;
    asm("cvt.rna.tf32.f32 %0, %1;" : "=r"(u) : "f"(f));
    return u;
}
__device__ __forceinline__ void mma_tf32(
    float& c0, float& c1, float& c2, float& c3,
    uint32_t a0, uint32_t a1, uint32_t a2, uint32_t a3,
    uint32_t b0, uint32_t b1)
{
    asm volatile(
        "mma.sync.aligned.m16n8k8.row.col.f32.tf32.tf32.f32 "
        "{%0,%1,%2,%3},{%4,%5,%6,%7},{%8,%9},{%0,%1,%2,%3};"
        : "+f"(c0), "+f"(c1), "+f"(c2), "+f"(c3)
        : "r"(a0), "r"(a1), "r"(a2), "r"(a3), "r"(b0), "r"(b1));
}
__device__ __forceinline__ void mma_f16(float* c, const uint32_t* a, const uint32_t* b) {
    asm volatile(
        "mma.sync.aligned.m16n8k16.row.col.f32.f16.f16.f32 "
        "{%0,%1,%2,%3},{%4,%5,%6,%7},{%8,%9},{%0,%1,%2,%3};"
        : "+f"(c[0]), "+f"(c[1]), "+f"(c[2]), "+f"(c[3])
        : "r"(a[0]), "r"(a[1]), "r"(a[2]), "r"(a[3]), "r"(b[0]), "r"(b[1]));
}
__device__ __forceinline__ uint32_t s2u(const void* p) {
    uint32_t a;
    asm("{ .reg .u64 t; cvta.to.shared.u64 t, %1; cvt.u32.u64 %0, t; }"
        : "=r"(a) : "l"(p));
    return a;
}
__device__ __forceinline__ void ldmx2t(uint32_t& b0, uint32_t& b1, uint32_t addr) {
    asm volatile("ldmatrix.sync.aligned.m8n8.x2.trans.shared.b16 {%0,%1}, [%2];"
                 : "=r"(b0), "=r"(b1) : "r"(addr));
}
__device__ __forceinline__ void ldmx4(uint32_t* r, uint32_t addr) {
    asm volatile("ldmatrix.sync.aligned.m8n8.x4.shared.b16 {%0,%1,%2,%3}, [%4];"
                 : "=r"(r[0]), "=r"(r[1]), "=r"(r[2]), "=r"(r[3]) : "r"(addr));
}
__device__ __forceinline__ void cp16(uint32_t dst, const void* src) {
    asm volatile("cp.async.ca.shared.global [%0], [%1], 16;" :: "r"(dst), "l"(src));
}

// ---------------- kernel 1: symmetrize + LN128 + @Wp, k<=l, write both ------
__global__ __launch_bounds__(256) void k_logits(
    const float* __restrict__ src, const float* __restrict__ Wp,
    const float* __restrict__ bp, const float* __restrict__ gn,
    const float* __restrict__ btn)
{
    int warp = (blockIdx.x * blockDim.x + threadIdx.x) >> 5;
    int lane = threadIdx.x & 31;
    if (warp >= LDIM * LDIM) return;
    int k = warp / LDIM, l = warp % LDIM;
    if (k > l) return;

    float4 a = *(const float4*)(src + ((size_t)k * LDIM + l) * DIN + lane * 4);
    float4 b = *(const float4*)(src + ((size_t)l * LDIM + k) * DIN + lane * 4);
    float x0 = 0.5f * (a.x + b.x), x1 = 0.5f * (a.y + b.y);
    float x2 = 0.5f * (a.z + b.z), x3 = 0.5f * (a.w + b.w);

    float m = warpSum(x0 + x1 + x2 + x3) * (1.0f / 128.0f);
    float d0 = x0 - m, d1 = x1 - m, d2 = x2 - m, d3 = x3 - m;
    float var = warpSum(d0*d0 + d1*d1 + d2*d2 + d3*d3) * (1.0f / 128.0f);
    float rinv = rsqrtf(var + 1e-5f);

    int i0 = lane * 4;
    float4 g  = *(const float4*)(gn  + i0);
    float4 bt = *(const float4*)(btn + i0);
    float y0 = g.x * d0 * rinv + bt.x;
    float y1 = g.y * d1 * rinv + bt.y;
    float y2 = g.z * d2 * rinv + bt.z;
    float y3 = g.w * d3 * rinv + bt.w;

    const float4* Wp4 = (const float4*)Wp;
    float4 w0 = Wp4[i0 + 0], w1 = Wp4[i0 + 1], w2 = Wp4[i0 + 2], w3 = Wp4[i0 + 3];

    float h0 = y0*w0.x + y1*w1.x + y2*w2.x + y3*w3.x;
    float h1 = y0*w0.y + y1*w1.y + y2*w2.y + y3*w3.y;
    float h2 = y0*w0.z + y1*w1.z + y2*w2.z + y3*w3.z;
    float h3 = y0*w0.w + y1*w1.w + y2*w2.w + y3*w3.w;
    h0 = warpSum(h0); h1 = warpSum(h1); h2 = warpSum(h2); h3 = warpSum(h3);

    if (lane == 0) {
        size_t p1 = (size_t)k * LDIM + l;
        size_t p2 = (size_t)l * LDIM + k;
        float v0 = h0 + bp[0], v1 = h1 + bp[1], v2 = h2 + bp[2], v3 = h3 + bp[3];
        g_attn[0 * LDIM * LDIM + p1] = v0; g_attn[0 * LDIM * LDIM + p2] = v0;
        g_attn[1 * LDIM * LDIM + p1] = v1; g_attn[1 * LDIM * LDIM + p2] = v1;
        g_attn[2 * LDIM * LDIM + p1] = v2; g_attn[2 * LDIM * LDIM + p2] = v2;
        g_attn[3 * LDIM * LDIM + p1] = v3; g_attn[3 * LDIM * LDIM + p2] = v3;
    }
}

// ---------------- kernel 2: softmax over k (reads row l; symmetric) ---------
__global__ __launch_bounds__(128) void k_softmax()
{
    int h = blockIdx.x / LDIM;
    int l = blockIdx.x % LDIM;
    const float* p = g_attn + ((size_t)h * LDIM + l) * LDIM;
    __half* q = g_attnh + ((size_t)h * LDIM + l) * LDIM;
    int t = threadIdx.x;

    float v0 = p[t], v1 = p[t + 128], v2 = p[t + 256];

    __shared__ float red[128];
    red[t] = fmaxf(v0, fmaxf(v1, v2));
    __syncthreads();
#pragma unroll
    for (int s = 64; s > 0; s >>= 1) {
        if (t < s) red[t] = fmaxf(red[t], red[t + s]);
        __syncthreads();
    }
    float mx = red[0];
    __syncthreads();

    float e0 = __expf(v0 - mx), e1 = __expf(v1 - mx), e2 = __expf(v2 - mx);
    red[t] = e0 + e1 + e2;
    __syncthreads();
#pragma unroll
    for (int s = 64; s > 0; s >>= 1) {
        if (t < s) red[t] += red[t + s];
        __syncthreads();
    }
    float rs = 1.0f / red[0];

    q[t      ] = __float2half_rn(e0 * rs);
    q[t + 128] = __float2half_rn(e1 * rs);
    q[t + 256] = __float2half_rn(e2 * rs);
}

// ---------------- kernel 3: fused LN(tgt) + @Wm + bm -> g_vh (half) ---------
__global__ __launch_bounds__(256) void k_vproj(
    const float* __restrict__ tgt, const float* __restrict__ Wm,
    const float* __restrict__ bm, const float* __restrict__ g1,
    const float* __restrict__ bt1)
{
    __shared__ uint32_t Aln[64 * 68];
    __shared__ uint32_t Bs[64 * 72];
    int r0 = blockIdx.x * 64;
    int tid = threadIdx.x, lane = tid & 31, wid = tid >> 5;
    int grp = lane >> 2, tig = lane & 3;

#pragma unroll
    for (int rr = 0; rr < 8; rr++) {
        int row = wid * 8 + rr;
        float2 v = *(const float2*)(tgt + (size_t)(r0 + row) * 64 + lane * 2);
        float m = warpSum(v.x + v.y) * (1.0f / 64.0f);
        float d0 = v.x - m, d1 = v.y - m;
        float var = warpSum(d0*d0 + d1*d1) * (1.0f / 64.0f);
        float rinv = rsqrtf(var + 1e-5f);
        float2 gg = *(const float2*)(g1 + lane * 2);
        float2 bb = *(const float2*)(bt1 + lane * 2);
        Aln[row * 68 + lane * 2    ] = f2tf(gg.x * d0 * rinv + bb.x);
        Aln[row * 68 + lane * 2 + 1] = f2tf(gg.y * d1 * rinv + bb.y);
    }
#pragma unroll
    for (int i = 0; i < 4; i++) {
        int idx4 = tid + i * 256;
        int row = idx4 >> 4, col4 = (idx4 & 15) * 4;
        float4 w = *(const float4*)(Wm + row * 64 + col4);
        uint32_t* d = &Bs[row * 72 + col4];
        d[0] = f2tf(w.x); d[1] = f2tf(w.y); d[2] = f2tf(w.z); d[3] = f2tf(w.w);
    }
    __syncthreads();

    int wm = wid >> 1, wn = wid & 1;
    float c[4][4] = {};
#pragma unroll
    for (int k0 = 0; k0 < 64; k0 += 8) {
        uint32_t a0 = Aln[(wm * 16 + grp    ) * 68 + k0 + tig];
        uint32_t a1 = Aln[(wm * 16 + grp + 8) * 68 + k0 + tig];
        uint32_t a2 = Aln[(wm * 16 + grp    ) * 68 + k0 + tig + 4];
        uint32_t a3 = Aln[(wm * 16 + grp + 8) * 68 + k0 + tig + 4];
#pragma unroll
        for (int nt = 0; nt < 4; nt++) {
            int bcol = wn * 32 + nt * 8 + grp;
            uint32_t b0 = Bs[(k0 + tig    ) * 72 + bcol];
            uint32_t b1 = Bs[(k0 + tig + 4) * 72 + bcol];
            mma_tf32(c[nt][0], c[nt][1], c[nt][2], c[nt][3], a0, a1, a2, a3, b0, b1);
        }
    }
#pragma unroll
    for (int nt = 0; nt < 4; nt++) {
        int col = wn * 32 + nt * 8 + 2 * tig;
#pragma unroll
        for (int q = 0; q < 4; q++) {
            int row = r0 + wm * 16 + grp + (q >= 2 ? 8 : 0);
            int cc  = col + (q & 1);
            float val = c[nt][q] + bm[cc];
            int n = row / LDIM, k = row % LDIM;
            g_vh[(((size_t)(cc & 3) * NSEQ + n) * 16 + (cc >> 2)) * LDIM + k] =
                __float2half_rn(val);
        }
    }
}

// ---------------- kernel 4: per-head attn GEMM fp16, ldmatrix + cp.async ----
#define KA_ST 40
#define KA_STAGE (128*KA_ST)
__global__ __launch_bounds__(256, 2) void k_attn()
{
    extern __shared__ __half sm[];
    __half* As = sm;
    __half* Bs = sm + 4 * KA_STAGE;
    const __half* A = g_vh    + (size_t)blockIdx.z * (NSEQ * 16 * LDIM);
    const __half* B = g_attnh + (size_t)blockIdx.z * (LDIM * LDIM);
    int bm = blockIdx.y * 128, bn = blockIdx.x * 128;
    int tid = threadIdx.x, lane = tid & 31, wid = tid >> 5;
    int wm = wid >> 2, wn = wid & 3, grp = lane >> 2, tig = lane & 3;
    uint32_t sA = s2u(As), sB = s2u(Bs);

    int crow = tid >> 2, cch = (tid & 3) * 8;
    int crow2 = (tid + 256) >> 2, cch2 = ((tid + 256) & 3) * 8;

    // ldmatrix lane-address components
    int aRow = wm * 64 + (lane & 15);           // + mt*16
    int aCol = (lane >> 4) * 8;                 // + ks*16
    int bRow = wn * 32 + ((lane >> 3) & 2) * 4 + (lane & 7);  // + ng*16
    int bCol = ((lane >> 3) & 1) * 8;           // + ks*16

    float c[4][4][4] = {};

#pragma unroll
    for (int p = 0; p < 3; p++) {
        int k0 = p * 32;
        cp16(sA + (p * KA_STAGE + crow  * KA_ST + cch ) * 2, A + (size_t)(bm + crow ) * LDIM + k0 + cch );
        cp16(sA + (p * KA_STAGE + crow2 * KA_ST + cch2) * 2, A + (size_t)(bm + crow2) * LDIM + k0 + cch2);
        cp16(sB + (p * KA_STAGE + crow  * KA_ST + cch ) * 2, B + (size_t)(bn + crow ) * LDIM + k0 + cch );
        cp16(sB + (p * KA_STAGE + crow2 * KA_ST + cch2) * 2, B + (size_t)(bn + crow2) * LDIM + k0 + cch2);
        asm volatile("cp.async.commit_group;");
    }

    for (int s = 0; s < 12; s++) {
        asm volatile("cp.async.wait_group 2;");
        __syncthreads();
        if (s + 3 < 12) {
            int buf = (s + 3) & 3, k0 = (s + 3) * 32;
            cp16(sA + (buf * KA_STAGE + crow  * KA_ST + cch ) * 2, A + (size_t)(bm + crow ) * LDIM + k0 + cch );
            cp16(sA + (buf * KA_STAGE + crow2 * KA_ST + cch2) * 2, A + (size_t)(bm + crow2) * LDIM + k0 + cch2);
            cp16(sB + (buf * KA_STAGE + crow  * KA_ST + cch ) * 2, B + (size_t)(bn + crow ) * LDIM + k0 + cch );
            cp16(sB + (buf * KA_STAGE + crow2 * KA_ST + cch2) * 2, B + (size_t)(bn + crow2) * LDIM + k0 + cch2);
        }
        asm volatile("cp.async.commit_group;");

        uint32_t sAb = sA + ((s & 3) * KA_STAGE) * 2;
        uint32_t sBb = sB + ((s & 3) * KA_STAGE) * 2;
#pragma unroll
        for (int ks = 0; ks < 2; ks++) {
            uint32_t a[4][4], bq[2][4];
#pragma unroll
            for (int mt = 0; mt < 4; mt++)
                ldmx4(a[mt], sAb + (((aRow + mt * 16) * KA_ST) + ks * 16 + aCol) * 2);
#pragma unroll
            for (int ng = 0; ng < 2; ng++)
                ldmx4(bq[ng], sBb + (((bRow + ng * 16) * KA_ST) + ks * 16 + bCol) * 2);
#pragma unroll
            for (int mt = 0; mt < 4; mt++)
#pragma unroll
                for (int nt = 0; nt < 4; nt++)
                    mma_f16(c[mt][nt], a[mt], &bq[nt >> 1][(nt & 1) * 2]);
        }
    }

    int h = blockIdx.z;
#pragma unroll
    for (int mt = 0; mt < 4; mt++)
#pragma unroll
        for (int nt = 0; nt < 4; nt++)
#pragma unroll
            for (int q = 0; q < 4; q++) {
                int row = bm + wm * 64 + mt * 16 + grp + ((q >= 2) ? 8 : 0);
                int col = bn + wn * 32 + nt * 8 + 2 * tig + (q & 1);
                int n = row >> 4, cc = row & 15;
                g_oh[((size_t)n * LDIM + col) * 64 + h * 16 + cc] =
                    __float2half_rn(c[mt][nt][q]);
            }
}

// ---------------- kernel 5: fused tail, 128 rows / 512 threads --------------
#define T_RAW 0                         // f32 [128][66]  33792
#define T_A   33792                     // half [128][72] 18432
#define T_HS  52224                     // half [128][264] 67584
#define T_W   119808                    // max 36864 (W2 256x72, W1 64x264)
#define SMEM_TAIL 156672

__global__ __launch_bounds__(512, 1) void k_tail(
    const float* __restrict__ tgt,
    const float* __restrict__ Wo, const float* __restrict__ bo,
    const float* __restrict__ W1, const float* __restrict__ b1,
    const float* __restrict__ W2, const float* __restrict__ b2,
    const float* __restrict__ g2, const float* __restrict__ bt2,
    float* __restrict__ out)
{
    extern __shared__ char smem[];
    float*   raw = (float*)(smem + T_RAW);
    __half*  Ah  = (__half*)(smem + T_A);
    __half*  Ws  = (__half*)(smem + T_W);
    uint32_t* AhU = (uint32_t*)Ah;
    uint32_t* HsU = (uint32_t*)(smem + T_HS);
    __half2*  Ws2 = (__half2*)Ws;
    __half2*  Hs2 = (__half2*)(smem + T_HS);
    __half2*  Ah2 = (__half2*)Ah;
    uint32_t sWs = s2u(Ws);

    int r0 = blockIdx.x * 128;
    int tid = threadIdx.x, lane = tid & 31, wid = tid >> 5;
    int grp = lane >> 2, tig = lane & 3;
    int lk = lane & 15;

    // ---- stage A0 (g_oh tile, channel-permuted) and Wo (row-permuted) ----
#pragma unroll
    for (int i = 0; i < 2; i++) {
        int idx = tid + i * 512;
        int row = idx >> 3, ch = (idx & 7) * 8;
        *(uint4*)(Ah + row * 72 + ch) = *(const uint4*)(g_oh + (size_t)(r0 + row) * 64 + ch);
    }
#pragma unroll
    for (int i = 0; i < 2; i++) {
        int idx = tid + i * 512;
        int k = idx >> 4, n4 = (idx & 15) * 4;
        float4 w = *(const float4*)(Wo + k * 64 + n4);
        int kp = (k & 3) * 16 + (k >> 2);
        Ws2[kp * 36 + n4 / 2    ] = __floats2half2_rn(w.x, w.y);
        Ws2[kp * 36 + n4 / 2 + 1] = __floats2half2_rn(w.z, w.w);
    }
    __syncthreads();

    // ---- GEMM0: mid = A0 @ Wo + bo + tgt -> raw  (16 warps: 8m x 2n) ----
    {
        int wm = wid >> 1, wn = wid & 1;
        int m0 = wm * 16, nb = wn * 32;
        float c[4][4] = {};
#pragma unroll
        for (int kw = 0; kw < 4; kw++) {
            uint32_t a[4];
            a[0] = AhU[(m0 + grp    ) * 36 + kw * 8 + tig];
            a[1] = AhU[(m0 + grp + 8) * 36 + kw * 8 + tig];
            a[2] = AhU[(m0 + grp    ) * 36 + kw * 8 + tig + 4];
            a[3] = AhU[(m0 + grp + 8) * 36 + kw * 8 + tig + 4];
#pragma unroll
            for (int nt = 0; nt < 4; nt++) {
                uint32_t b[2];
                ldmx2t(b[0], b[1], sWs + ((kw * 16 + lk) * 72 + nb + nt * 8) * 2);
                mma_f16(c[nt], a, b);
            }
        }
#pragma unroll
        for (int nt = 0; nt < 4; nt++)
#pragma unroll
            for (int q = 0; q < 4; q++) {
                int lrow = m0 + grp + ((q >= 2) ? 8 : 0);
                int cc = nb + nt * 8 + 2 * tig + (q & 1);
                raw[lrow * 66 + cc] = c[nt][q] + bo[cc] + tgt[(size_t)(r0 + lrow) * 64 + cc];
            }
    }
    __syncthreads();

    // ---- LN(raw) -> Ah; stage W1 ----
#pragma unroll
    for (int rr = 0; rr < 8; rr++) {
        int row = wid * 8 + rr;
        float x0 = raw[row * 66 + lane * 2], x1 = raw[row * 66 + lane * 2 + 1];
        float m = warpSum(x0 + x1) * (1.0f / 64.0f);
        float d0 = x0 - m, d1 = x1 - m;
        float var = warpSum(d0*d0 + d1*d1) * (1.0f / 64.0f);
        float rinv = rsqrtf(var + 1e-5f);
        float2 gg = *(const float2*)(g2 + lane * 2);
        float2 bb = *(const float2*)(bt2 + lane * 2);
        Ah2[row * 36 + lane] = __floats2half2_rn(gg.x * d0 * rinv + bb.x,
                                                 gg.y * d1 * rinv + bb.y);
    }
#pragma unroll
    for (int i = 0; i < 8; i++) {
        int idx = tid + i * 512;
        int k = idx >> 6, n4 = (idx & 63) * 4;
        float4 w = *(const float4*)(W1 + k * DFF + n4);
        Ws2[k * 132 + n4 / 2    ] = __floats2half2_rn(w.x, w.y);
        Ws2[k * 132 + n4 / 2 + 1] = __floats2half2_rn(w.z, w.w);
    }
    __syncthreads();

    // ---- GEMM1: hidden = relu(Ah @ W1 + b1) -> Hs  (16 warps: 4m x 4n) ----
    {
        int wm = wid >> 2, wn = wid & 3;
        float c[2][8][4] = {};
#pragma unroll
        for (int kw = 0; kw < 4; kw++) {
            uint32_t a[2][4];
#pragma unroll
            for (int mt = 0; mt < 2; mt++) {
                int r = wm * 32 + mt * 16 + grp;
                a[mt][0] = AhU[(r    ) * 36 + kw * 8 + tig];
                a[mt][1] = AhU[(r + 8) * 36 + kw * 8 + tig];
                a[mt][2] = AhU[(r    ) * 36 + kw * 8 + tig + 4];
                a[mt][3] = AhU[(r + 8) * 36 + kw * 8 + tig + 4];
            }
#pragma unroll
            for (int nt = 0; nt < 8; nt++) {
                uint32_t b[2];
                ldmx2t(b[0], b[1], sWs + ((kw * 16 + lk) * 264 + wn * 64 + nt * 8) * 2);
#pragma unroll
                for (int mt = 0; mt < 2; mt++) mma_f16(c[mt][nt], a[mt], b);
            }
        }
#pragma unroll
        for (int mt = 0; mt < 2; mt++)
#pragma unroll
            for (int nt = 0; nt < 8; nt++)
#pragma unroll
                for (int q2 = 0; q2 < 2; q2++) {
                    int row = wm * 32 + mt * 16 + grp + q2 * 8;
                    int col = wn * 64 + nt * 8 + 2 * tig;
                    float v0 = fmaxf(c[mt][nt][q2 * 2 + 0] + b1[col    ], 0.f);
                    float v1 = fmaxf(c[mt][nt][q2 * 2 + 1] + b1[col + 1], 0.f);
                    Hs2[row * 132 + col / 2] = __floats2half2_rn(v0, v1);
                }
    }
    __syncthreads();

    // ---- stage W2 ----
#pragma unroll
    for (int i = 0; i < 8; i++) {
        int idx = tid + i * 512;
        int k = idx >> 4, n4 = (idx & 15) * 4;
        float4 w = *(const float4*)(W2 + k * 64 + n4);
        Ws2[k * 36 + n4 / 2    ] = __floats2half2_rn(w.x, w.y);
        Ws2[k * 36 + n4 / 2 + 1] = __floats2half2_rn(w.z, w.w);
    }
    __syncthreads();

    // ---- GEMM2: out = Hs @ W2 + b2 + raw  (16 warps: 8m x 2n) ----
    {
        int wm = wid >> 1, wn = wid & 1;
        int m0 = wm * 16, nb = wn * 32;
        float c[4][4] = {};
#pragma unroll
        for (int kw = 0; kw < 16; kw++) {
            uint32_t a[4];
            a[0] = HsU[(m0 + grp    ) * 132 + kw * 8 + tig];
            a[1] = HsU[(m0 + grp + 8) * 132 + kw * 8 + tig];
            a[2] = HsU[(m0 + grp    ) * 132 + kw * 8 + tig + 4];
            a[3] = HsU[(m0 + grp + 8) * 132 + kw * 8 + tig + 4];
#pragma unroll
            for (int nt = 0; nt < 4; nt++) {
                uint32_t b[2];
                ldmx2t(b[0], b[1], sWs + ((kw * 16 + lk) * 72 + nb + nt * 8) * 2);
                mma_f16(c[nt], a, b);
            }
        }
#pragma unroll
        for (int nt = 0; nt < 4; nt++)
#pragma unroll
            for (int q = 0; q < 4; q++) {
                int lrow = m0 + grp + ((q >= 2) ? 8 : 0);
                int cc = nb + nt * 8 + 2 * tig + (q & 1);
                out[(size_t)(r0 + lrow) * 64 + cc] = c[nt][q] + b2[cc] + raw[lrow * 66 + cc];
            }
    }
}

// ---------------- launch ------------------------------------------------------
extern "C" void kernel_launch(void* const* d_in, const int* in_sizes, int n_in,
                              void* d_out, int out_size)
{
    const float* src = (const float*)d_in[0];
    const float* tgt = (const float*)d_in[1];
    const float* Wp  = (const float*)d_in[2];
    const float* bp  = (const float*)d_in[3];
    const float* Wm  = (const float*)d_in[4];
    const float* bm  = (const float*)d_in[5];
    const float* Wo  = (const float*)d_in[6];
    const float* bo  = (const float*)d_in[7];
    const float* W1  = (const float*)d_in[8];
    const float* b1  = (const float*)d_in[9];
    const float* W2  = (const float*)d_in[10];
    const float* b2  = (const float*)d_in[11];
    const float* gn  = (const float*)d_in[12];
    const float* btn = (const float*)d_in[13];
    const float* g1  = (const float*)d_in[14];
    const float* bt1 = (const float*)d_in[15];
    const float* g2  = (const float*)d_in[16];
    const float* bt2 = (const float*)d_in[17];
    float* out = (float*)d_out;

    const int smem_attn = 4 * KA_STAGE * 2 * 2;   // 81920
    cudaFuncSetAttribute(k_attn, cudaFuncAttributeMaxDynamicSharedMemorySize, smem_attn);
    cudaFuncSetAttribute(k_tail, cudaFuncAttributeMaxDynamicSharedMemorySize, SMEM_TAIL);

    k_logits<<<(LDIM * LDIM) / 8, 256>>>(src, Wp, bp, gn, btn);
    k_softmax<<<HEADS * LDIM, 128>>>();
    k_vproj<<<TOK / 64, 256>>>(tgt, Wm, bm, g1, bt1);
    k_attn<<<dim3(LDIM / 128, (NSEQ * 16) / 128, HEADS), 256, smem_attn>>>();
    k_tail<<<TOK / 128, 512, SMEM_TAIL>>>(tgt, Wo, bo, W1, b1, W2, b2, g2, bt2, out);
}